// round 2
// baseline (speedup 1.0000x reference)
#include <cuda_runtime.h>
#include <cuda_bf16.h>
#include <math.h>

#define LL   5
#define BB   256
#define HH   512
#define GG   2048
#define SS   128
#define VV   32000
#define KTOT 1024

#define NCTA 128
#define NTHR 256
#define BM   32
#define KT   32
#define NKT  (KTOT / KT)   // 32
#define NKTO (HH / KT)     // 16

// Persistent state (device globals: allocation-free scratch).
// h is double-buffered by step parity; c is updated in place (each (b,u) owned
// by exactly one thread of one CTA, so no cross-CTA hazard).
__device__ float g_h[2][LL][BB][HH];
__device__ float g_c[LL][BB][HH];
__device__ unsigned g_bar_count;  // zero-initialized
__device__ unsigned g_bar_gen;

__device__ __forceinline__ float sigf(float v) { return 1.0f / (1.0f + expf(-v)); }

// Software grid barrier. Safe: grid = 128 CTAs <= 148 SMs, __launch_bounds__
// guarantees 1-CTA residency, so all CTAs are co-resident in wave 1.
// Generation-based, deterministic, replay-safe (gen monotonically increases
// across graph replays; count always returns to 0).
__device__ __forceinline__ void grid_sync() {
    __syncthreads();
    if (threadIdx.x == 0) {
        __threadfence();
        unsigned gen = *((volatile unsigned*)&g_bar_gen);
        if (atomicAdd(&g_bar_count, 1u) == NCTA - 1u) {
            atomicExch(&g_bar_count, 0u);
            __threadfence();
            atomicAdd(&g_bar_gen, 1u);
        } else {
            while (*((volatile unsigned*)&g_bar_gen) == gen) { __nanosleep(32); }
        }
        __threadfence();
    }
    __syncthreads();
}

// CTA tiling: 128 CTAs = 8 batch-tiles (32 rows) x 16 unit-tiles (32 hidden units).
// Each CTA computes a 32x128 tile of gates where the 128 columns are
// gate-INTERLEAVED: local n = u*4 + gate, so each thread's 4 consecutive
// columns are (i,f,g,o) of ONE unit -> activation is done fully in registers.
__global__ void __launch_bounds__(NTHR, 1)
lstm_persistent(const int* __restrict__ x,
                const float* __restrict__ h0,
                const float* __restrict__ c0,
                const float* __restrict__ emb,
                const float* __restrict__ Wih_g,
                const float* __restrict__ Whh_g,
                const float* __restrict__ bih_g,
                const float* __restrict__ bhh_g,
                const float* __restrict__ Wout,
                const float* __restrict__ bout,
                float* __restrict__ out)
{
    __shared__ __align__(16) float A_s[KT][36];   // A^T: [k][batch], pad 36 keeps float4 16B-aligned (144B rows)
    __shared__ __align__(16) float W_s[KT][132];  // W^T: [k][gatecol], pad 132 (528B rows)
    __shared__ int tok_s[BM];

    const int tid = threadIdx.x;
    const int bid = blockIdx.x;
    const int mb  = bid >> 4;        // batch tile 0..7
    const int nb  = bid & 15;        // unit tile 0..15
    const int ty  = tid >> 5;        // 0..7  -> 4 batch rows each
    const int tx  = tid & 31;        // 0..31 -> one unit (4 gate cols)
    const int lb  = tid >> 3;        // 0..31 load row
    const int kc  = (tid & 7) << 2;  // 0..28 load k offset

    // ---- init: h0 -> parity-1 buffer (prev of step 0), c0 -> c ----
    for (int i = bid * NTHR + tid; i < LL * BB * HH; i += NCTA * NTHR) {
        ((float*)g_h)[LL * BB * HH + i] = h0[i];
        ((float*)g_c)[i] = c0[i];
    }
    grid_sync();

    for (int t = 0; t < SS; ++t) {
        const int cur  = t & 1;
        const int prev = cur ^ 1;
        // torch .view(S,B,-1) reinterpretation: token(t,b) = x_flat[t*B + b]
        if (tid < BM) tok_s[tid] = x[t * BB + mb * BM + tid];
        __syncthreads();

        #pragma unroll 1
        for (int l = 0; l < LL; ++l) {
            const float* __restrict__ hpv = &g_h[prev][l][0][0];
            const float* __restrict__ hin = &g_h[cur][(l == 0 ? 0 : l - 1)][0][0];
            const float* __restrict__ Wih = Wih_g + l * GG * HH;
            const float* __restrict__ Whh = Whh_g + l * GG * HH;
            const bool use_emb = (l == 0);

            float acc[4][4];
            #pragma unroll
            for (int i = 0; i < 4; ++i)
                #pragma unroll
                for (int j = 0; j < 4; ++j) acc[i][j] = 0.0f;

            float4 av, wv[4];
            // prologue: load k-tile 0 (k = kc < 512, always the "input" half)
            {
                const float* ar = use_emb ? (emb + (size_t)tok_s[lb] * HH + kc)
                                          : (hin + (size_t)(mb * BM + lb) * HH + kc);
                av = *(const float4*)ar;
                #pragma unroll
                for (int j = 0; j < 4; ++j) {
                    const int n = lb + 32 * j;                       // gate-interleaved col
                    const int grow = (n & 3) * HH + nb * 32 + (n >> 2);
                    wv[j] = *(const float4*)(Wih + (size_t)grow * HH + kc);
                }
            }

            #pragma unroll 1
            for (int kt = 0; kt < NKT; ++kt) {
                __syncthreads();   // previous compute done reading smem
                A_s[kc + 0][lb] = av.x; A_s[kc + 1][lb] = av.y;
                A_s[kc + 2][lb] = av.z; A_s[kc + 3][lb] = av.w;
                #pragma unroll
                for (int j = 0; j < 4; ++j) {
                    const int n = lb + 32 * j;
                    W_s[kc + 0][n] = wv[j].x; W_s[kc + 1][n] = wv[j].y;
                    W_s[kc + 2][n] = wv[j].z; W_s[kc + 3][n] = wv[j].w;
                }
                __syncthreads();
                if (kt + 1 < NKT) {   // software pipeline: next tile loads overlap compute
                    const int k = (kt + 1) * KT + kc;
                    const float* ar;
                    if (k < HH) ar = use_emb ? (emb + (size_t)tok_s[lb] * HH + k)
                                             : (hin + (size_t)(mb * BM + lb) * HH + k);
                    else        ar = hpv + (size_t)(mb * BM + lb) * HH + (k - HH);
                    av = *(const float4*)ar;
                    #pragma unroll
                    for (int j = 0; j < 4; ++j) {
                        const int n = lb + 32 * j;
                        const int grow = (n & 3) * HH + nb * 32 + (n >> 2);
                        wv[j] = (k < HH) ? *(const float4*)(Wih + (size_t)grow * HH + k)
                                         : *(const float4*)(Whh + (size_t)grow * HH + (k - HH));
                    }
                }
                #pragma unroll
                for (int kk = 0; kk < KT; ++kk) {
                    const float4 a = *(const float4*)(&A_s[kk][ty << 2]);  // warp-broadcast
                    const float4 w = *(const float4*)(&W_s[kk][tx << 2]);  // conflict-free
                    acc[0][0] += a.x * w.x; acc[0][1] += a.x * w.y; acc[0][2] += a.x * w.z; acc[0][3] += a.x * w.w;
                    acc[1][0] += a.y * w.x; acc[1][1] += a.y * w.y; acc[1][2] += a.y * w.z; acc[1][3] += a.y * w.w;
                    acc[2][0] += a.z * w.x; acc[2][1] += a.z * w.y; acc[2][2] += a.z * w.z; acc[2][3] += a.z * w.w;
                    acc[3][0] += a.w * w.x; acc[3][1] += a.w * w.y; acc[3][2] += a.w * w.z; acc[3][3] += a.w * w.w;
                }
            }

            // ---- activation: thread owns unit u for 4 batches, all 4 gates ----
            const int u = nb * 32 + tx;
            const float bi = bih_g[l * GG + u]           + bhh_g[l * GG + u];
            const float bf = bih_g[l * GG + HH + u]      + bhh_g[l * GG + HH + u];
            const float bg = bih_g[l * GG + 2 * HH + u]  + bhh_g[l * GG + 2 * HH + u];
            const float bo = bih_g[l * GG + 3 * HH + u]  + bhh_g[l * GG + 3 * HH + u];
            #pragma unroll
            for (int i = 0; i < 4; ++i) {
                const int b = mb * BM + (ty << 2) + i;
                const float ig = sigf(acc[i][0] + bi);
                const float fg = sigf(acc[i][1] + bf);
                const float gg = tanhf(acc[i][2] + bg);
                const float og = sigf(acc[i][3] + bo);
                const float cn = fg * g_c[l][b][u] + ig * gg;
                g_c[l][b][u] = cn;
                g_h[cur][l][b][u] = og * tanhf(cn);
            }
            grid_sync();   // h[cur][l] complete before layer l+1 reads it
        }
    }

    // ---- output GEMM: logits(256 x 32000) = h_final @ Wout^T + bout ----
    // 2000 independent 32x128 tiles, persistent-looped over 128 CTAs.
    const float* __restrict__ hfin = &g_h[(SS - 1) & 1][LL - 1][0][0];
    #pragma unroll 1
    for (int tile = bid; tile < 8 * 250; tile += NCTA) {
        const int b0 = (tile / 250) * 32;
        const int v0 = (tile % 250) * 128;
        float acc[4][4];
        #pragma unroll
        for (int i = 0; i < 4; ++i)
            #pragma unroll
            for (int j = 0; j < 4; ++j) acc[i][j] = 0.0f;

        float4 av, wv[4];
        av = *(const float4*)(hfin + (size_t)(b0 + lb) * HH + kc);
        #pragma unroll
        for (int j = 0; j < 4; ++j)
            wv[j] = *(const float4*)(Wout + (size_t)(v0 + lb + 32 * j) * HH + kc);

        #pragma unroll 1
        for (int kt = 0; kt < NKTO; ++kt) {
            __syncthreads();
            A_s[kc + 0][lb] = av.x; A_s[kc + 1][lb] = av.y;
            A_s[kc + 2][lb] = av.z; A_s[kc + 3][lb] = av.w;
            #pragma unroll
            for (int j = 0; j < 4; ++j) {
                const int n = lb + 32 * j;    // plain mapping: col n -> v0+n
                W_s[kc + 0][n] = wv[j].x; W_s[kc + 1][n] = wv[j].y;
                W_s[kc + 2][n] = wv[j].z; W_s[kc + 3][n] = wv[j].w;
            }
            __syncthreads();
            if (kt + 1 < NKTO) {
                const int k = (kt + 1) * KT + kc;
                av = *(const float4*)(hfin + (size_t)(b0 + lb) * HH + k);
                #pragma unroll
                for (int j = 0; j < 4; ++j)
                    wv[j] = *(const float4*)(Wout + (size_t)(v0 + lb + 32 * j) * HH + k);
            }
            #pragma unroll
            for (int kk = 0; kk < KT; ++kk) {
                const float4 a = *(const float4*)(&A_s[kk][ty << 2]);
                const float4 w = *(const float4*)(&W_s[kk][tx << 2]);
                acc[0][0] += a.x * w.x; acc[0][1] += a.x * w.y; acc[0][2] += a.x * w.z; acc[0][3] += a.x * w.w;
                acc[1][0] += a.y * w.x; acc[1][1] += a.y * w.y; acc[1][2] += a.y * w.z; acc[1][3] += a.y * w.w;
                acc[2][0] += a.z * w.x; acc[2][1] += a.z * w.y; acc[2][2] += a.z * w.z; acc[2][3] += a.z * w.w;
                acc[3][0] += a.w * w.x; acc[3][1] += a.w * w.y; acc[3][2] += a.w * w.z; acc[3][3] += a.w * w.w;
            }
        }
        #pragma unroll
        for (int i = 0; i < 4; ++i) {
            const int b = b0 + (ty << 2) + i;
            const int v = v0 + (tx << 2);
            float4 r;
            r.x = acc[i][0] + bout[v + 0];
            r.y = acc[i][1] + bout[v + 1];
            r.z = acc[i][2] + bout[v + 2];
            r.w = acc[i][3] + bout[v + 3];
            *(float4*)(out + (size_t)b * VV + v) = r;
        }
    }
}

extern "C" void kernel_launch(void* const* d_in, const int* in_sizes, int n_in,
                              void* d_out, int out_size) {
    (void)in_sizes; (void)n_in; (void)out_size;
    lstm_persistent<<<NCTA, NTHR>>>(
        (const int*)  d_in[0],   // x        (B,S) int32
        (const float*)d_in[1],   // h0       (L,B,H)
        (const float*)d_in[2],   // c0       (L,B,H)
        (const float*)d_in[3],   // emb      (V,H)
        (const float*)d_in[4],   // W_ih     (L,4H,H)
        (const float*)d_in[5],   // W_hh     (L,4H,H)
        (const float*)d_in[6],   // b_ih     (L,4H)
        (const float*)d_in[7],   // b_hh     (L,4H)
        (const float*)d_in[8],   // W_out    (V,H)
        (const float*)d_in[9],   // b_out    (V,)
        (float*)d_out);          // (B,V) float32
}

// round 4
// speedup vs baseline: 1.6338x; 1.6338x over previous
#include <cuda_runtime.h>
#include <cuda_bf16.h>
#include <math.h>

#define LL   5
#define BB   256
#define HH   512
#define GG   2048
#define SS   128
#define VV   32000
#define KTOT 1024

#define NCTA 128
#define NTHR 256
#define BM   32
#define KT   32
#define NKT  (KTOT / KT)   // 32
#define NKTO (HH / KT)     // 16

// Persistent state (device globals: allocation-free scratch).
// h is double-buffered by step parity; c is updated in place (each (b,u) owned
// by exactly one thread of one CTA, so no cross-CTA hazard).
__device__ float g_h[2][LL][BB][HH];
__device__ float g_c[LL][BB][HH];
__device__ unsigned g_bar_count;  // zero-initialized
__device__ unsigned g_bar_gen;

__device__ __forceinline__ float sigf(float v) { return 1.0f / (1.0f + expf(-v)); }

// Software grid barrier. Safe: grid = 128 CTAs <= 148 SMs, __launch_bounds__
// guarantees 1-CTA residency, so all CTAs are co-resident in wave 1.
// Generation-based, deterministic, replay-safe (gen monotonically increases
// across graph replays; count always returns to 0).
__device__ __forceinline__ void grid_sync() {
    __syncthreads();
    if (threadIdx.x == 0) {
        __threadfence();
        unsigned gen = *((volatile unsigned*)&g_bar_gen);
        if (atomicAdd(&g_bar_count, 1u) == NCTA - 1u) {
            atomicExch(&g_bar_count, 0u);
            __threadfence();
            atomicAdd(&g_bar_gen, 1u);
        } else {
            while (*((volatile unsigned*)&g_bar_gen) == gen) { __nanosleep(32); }
        }
        __threadfence();
    }
    __syncthreads();
}

// CTA tiling: 128 CTAs = 8 batch-tiles (32 rows) x 16 unit-tiles (32 hidden units).
// Each CTA computes a 32x128 tile of gates where the 128 columns are
// gate-INTERLEAVED: local n = u*4 + gate, so each thread's 4 consecutive
// columns are (i,f,g,o) of ONE unit -> activation is done fully in registers.
__global__ void __launch_bounds__(NTHR, 1)
lstm_persistent(const int* __restrict__ x,
                const float* __restrict__ h0,
                const float* __restrict__ c0,
                const float* __restrict__ emb,
                const float* __restrict__ Wih_g,
                const float* __restrict__ Whh_g,
                const float* __restrict__ bih_g,
                const float* __restrict__ bhh_g,
                const float* __restrict__ Wout,
                const float* __restrict__ bout,
                float* __restrict__ out)
{
    __shared__ __align__(16) float A_s[KT][36];   // A^T: [k][batch], pad 36 keeps float4 16B-aligned (144B rows)
    __shared__ __align__(16) float W_s[KT][132];  // W^T: [k][gatecol], pad 132 (528B rows)
    __shared__ int tok_s[BM];

    const int tid = threadIdx.x;
    const int bid = blockIdx.x;
    const int mb  = bid >> 4;        // batch tile 0..7
    const int nb  = bid & 15;        // unit tile 0..15
    const int ty  = tid >> 5;        // 0..7  -> 4 batch rows each
    const int tx  = tid & 31;        // 0..31 -> one unit (4 gate cols)
    const int lb  = tid >> 3;        // 0..31 load row
    const int kc  = (tid & 7) << 2;  // 0..28 load k offset

    // ---- init: h0 -> parity-1 buffer (prev of step 0), c0 -> c ----
    for (int i = bid * NTHR + tid; i < LL * BB * HH; i += NCTA * NTHR) {
        ((float*)g_h)[LL * BB * HH + i] = h0[i];
        ((float*)g_c)[i] = c0[i];
    }
    grid_sync();

    for (int t = 0; t < SS; ++t) {
        const int cur  = t & 1;
        const int prev = cur ^ 1;
        // torch .view(S,B,-1) reinterpretation: token(t,b) = x_flat[t*B + b]
        if (tid < BM) tok_s[tid] = x[t * BB + mb * BM + tid];
        __syncthreads();

        #pragma unroll 1
        for (int l = 0; l < LL; ++l) {
            const float* __restrict__ hpv = &g_h[prev][l][0][0];
            const float* __restrict__ hin = &g_h[cur][(l == 0 ? 0 : l - 1)][0][0];
            const float* __restrict__ Wih = Wih_g + l * GG * HH;
            const float* __restrict__ Whh = Whh_g + l * GG * HH;
            const bool use_emb = (l == 0);

            float acc[4][4];
            #pragma unroll
            for (int i = 0; i < 4; ++i)
                #pragma unroll
                for (int j = 0; j < 4; ++j) acc[i][j] = 0.0f;

            float4 av, wv[4];
            // prologue: load k-tile 0 (k = kc < 512, always the "input" half)
            {
                const float* ar = use_emb ? (emb + (size_t)tok_s[lb] * HH + kc)
                                          : (hin + (size_t)(mb * BM + lb) * HH + kc);
                av = *(const float4*)ar;
                #pragma unroll
                for (int j = 0; j < 4; ++j) {
                    const int n = lb + 32 * j;                       // gate-interleaved col
                    const int grow = (n & 3) * HH + nb * 32 + (n >> 2);
                    wv[j] = *(const float4*)(Wih + (size_t)grow * HH + kc);
                }
            }

            #pragma unroll 1
            for (int kt = 0; kt < NKT; ++kt) {
                __syncthreads();   // previous compute done reading smem
                A_s[kc + 0][lb] = av.x; A_s[kc + 1][lb] = av.y;
                A_s[kc + 2][lb] = av.z; A_s[kc + 3][lb] = av.w;
                #pragma unroll
                for (int j = 0; j < 4; ++j) {
                    const int n = lb + 32 * j;
                    W_s[kc + 0][n] = wv[j].x; W_s[kc + 1][n] = wv[j].y;
                    W_s[kc + 2][n] = wv[j].z; W_s[kc + 3][n] = wv[j].w;
                }
                __syncthreads();
                if (kt + 1 < NKT) {   // software pipeline: next tile loads overlap compute
                    const int k = (kt + 1) * KT + kc;
                    const float* ar;
                    if (k < HH) ar = use_emb ? (emb + (size_t)tok_s[lb] * HH + k)
                                             : (hin + (size_t)(mb * BM + lb) * HH + k);
                    else        ar = hpv + (size_t)(mb * BM + lb) * HH + (k - HH);
                    av = *(const float4*)ar;
                    #pragma unroll
                    for (int j = 0; j < 4; ++j) {
                        const int n = lb + 32 * j;
                        const int grow = (n & 3) * HH + nb * 32 + (n >> 2);
                        wv[j] = (k < HH) ? *(const float4*)(Wih + (size_t)grow * HH + k)
                                         : *(const float4*)(Whh + (size_t)grow * HH + (k - HH));
                    }
                }
                #pragma unroll
                for (int kk = 0; kk < KT; ++kk) {
                    const float4 a = *(const float4*)(&A_s[kk][ty << 2]);  // warp-broadcast
                    const float4 w = *(const float4*)(&W_s[kk][tx << 2]);  // conflict-free
                    acc[0][0] += a.x * w.x; acc[0][1] += a.x * w.y; acc[0][2] += a.x * w.z; acc[0][3] += a.x * w.w;
                    acc[1][0] += a.y * w.x; acc[1][1] += a.y * w.y; acc[1][2] += a.y * w.z; acc[1][3] += a.y * w.w;
                    acc[2][0] += a.z * w.x; acc[2][1] += a.z * w.y; acc[2][2] += a.z * w.z; acc[2][3] += a.z * w.w;
                    acc[3][0] += a.w * w.x; acc[3][1] += a.w * w.y; acc[3][2] += a.w * w.z; acc[3][3] += a.w * w.w;
                }
            }

            // ---- activation: thread owns unit u for 4 batches, all 4 gates ----
            const int u = nb * 32 + tx;
            const float bi = bih_g[l * GG + u]           + bhh_g[l * GG + u];
            const float bf = bih_g[l * GG + HH + u]      + bhh_g[l * GG + HH + u];
            const float bg = bih_g[l * GG + 2 * HH + u]  + bhh_g[l * GG + 2 * HH + u];
            const float bo = bih_g[l * GG + 3 * HH + u]  + bhh_g[l * GG + 3 * HH + u];
            #pragma unroll
            for (int i = 0; i < 4; ++i) {
                const int b = mb * BM + (ty << 2) + i;
                const float ig = sigf(acc[i][0] + bi);
                const float fg = sigf(acc[i][1] + bf);
                const float gg = tanhf(acc[i][2] + bg);
                const float og = sigf(acc[i][3] + bo);
                const float cn = fg * g_c[l][b][u] + ig * gg;
                g_c[l][b][u] = cn;
                g_h[cur][l][b][u] = og * tanhf(cn);
            }
            grid_sync();   // h[cur][l] complete before layer l+1 reads it
        }
    }

    // ---- output GEMM: logits(256 x 32000) = h_final @ Wout^T + bout ----
    // 2000 independent 32x128 tiles, persistent-looped over 128 CTAs.
    const float* __restrict__ hfin = &g_h[(SS - 1) & 1][LL - 1][0][0];
    #pragma unroll 1
    for (int tile = bid; tile < 8 * 250; tile += NCTA) {
        const int b0 = (tile / 250) * 32;
        const int v0 = (tile % 250) * 128;
        float acc[4][4];
        #pragma unroll
        for (int i = 0; i < 4; ++i)
            #pragma unroll
            for (int j = 0; j < 4; ++j) acc[i][j] = 0.0f;

        float4 av, wv[4];
        av = *(const float4*)(hfin + (size_t)(b0 + lb) * HH + kc);
        #pragma unroll
        for (int j = 0; j < 4; ++j)
            wv[j] = *(const float4*)(Wout + (size_t)(v0 + lb + 32 * j) * HH + kc);

        #pragma unroll 1
        for (int kt = 0; kt < NKTO; ++kt) {
            __syncthreads();
            A_s[kc + 0][lb] = av.x; A_s[kc + 1][lb] = av.y;
            A_s[kc + 2][lb] = av.z; A_s[kc + 3][lb] = av.w;
            #pragma unroll
            for (int j = 0; j < 4; ++j) {
                const int n = lb + 32 * j;    // plain mapping: col n -> v0+n
                W_s[kc + 0][n] = wv[j].x; W_s[kc + 1][n] = wv[j].y;
                W_s[kc + 2][n] = wv[j].z; W_s[kc + 3][n] = wv[j].w;
            }
            __syncthreads();
            if (kt + 1 < NKTO) {
                const int k = (kt + 1) * KT + kc;
                av = *(const float4*)(hfin + (size_t)(b0 + lb) * HH + k);
                #pragma unroll
                for (int j = 0; j < 4; ++j)
                    wv[j] = *(const float4*)(Wout + (size_t)(v0 + lb + 32 * j) * HH + k);
            }
            #pragma unroll
            for (int kk = 0; kk < KT; ++kk) {
                const float4 a = *(const float4*)(&A_s[kk][ty << 2]);
                const float4 w = *(const float4*)(&W_s[kk][tx << 2]);
                acc[0][0] += a.x * w.x; acc[0][1] += a.x * w.y; acc[0][2] += a.x * w.z; acc[0][3] += a.x * w.w;
                acc[1][0] += a.y * w.x; acc[1][1] += a.y * w.y; acc[1][2] += a.y * w.z; acc[1][3] += a.y * w.w;
                acc[2][0] += a.z * w.x; acc[2][1] += a.z * w.y; acc[2][2] += a.z * w.z; acc[2][3] += a.z * w.w;
                acc[3][0] += a.w * w.x; acc[3][1] += a.w * w.y; acc[3][2] += a.w * w.z; acc[3][3] += a.w * w.w;
            }
        }
        #pragma unroll
        for (int i = 0; i < 4; ++i) {
            const int b = b0 + (ty << 2) + i;
            const int v = v0 + (tx << 2);
            float4 r;
            r.x = acc[i][0] + bout[v + 0];
            r.y = acc[i][1] + bout[v + 1];
            r.z = acc[i][2] + bout[v + 2];
            r.w = acc[i][3] + bout[v + 3];
            *(float4*)(out + (size_t)b * VV + v) = r;
        }
    }
}

extern "C" void kernel_launch(void* const* d_in, const int* in_sizes, int n_in,
                              void* d_out, int out_size) {
    (void)in_sizes; (void)n_in; (void)out_size;
    lstm_persistent<<<NCTA, NTHR>>>(
        (const int*)  d_in[0],   // x        (B,S) int32
        (const float*)d_in[1],   // h0       (L,B,H)
        (const float*)d_in[2],   // c0       (L,B,H)
        (const float*)d_in[3],   // emb      (V,H)
        (const float*)d_in[4],   // W_ih     (L,4H,H)
        (const float*)d_in[5],   // W_hh     (L,4H,H)
        (const float*)d_in[6],   // b_ih     (L,4H)
        (const float*)d_in[7],   // b_hh     (L,4H)
        (const float*)d_in[8],   // W_out    (V,H)
        (const float*)d_in[9],   // b_out    (V,)
        (float*)d_out);          // (B,V) float32
}

// round 6
// speedup vs baseline: 2.6834x; 1.6424x over previous
#include <cuda_runtime.h>
#include <cuda_bf16.h>
#include <math.h>
#include <stdint.h>

#define LL 5
#define BB 256
#define HH 512
#define GG 2048
#define SSTEPS 128
#define VV 32000
#define KTOT 1024

#define NCTA 64
#define NTHR 256
#define KC 64          // k elems per chunk (64 bf16 = 128B row = SW128 atom)
#define NCH 16         // chunks per layer GEMM (K=1024)
#define NCHO 8         // chunks per output GEMM (K=512)

// dynamic SMEM layout (bytes)
#define SM_BIAS  128   // 5*64 floats
#define SM_TBASE 2048
#define SM_BUF   49152 // A_hi 16K | A_lo 16K | W_hi 8K | W_lo 8K
#define OFF_AH 0
#define OFF_AL 16384
#define OFF_WH 32768
#define OFF_WL 40960
#define SMEM_TOTAL (SM_TBASE + 2*SM_BUF)   // 100352
#define GS_STRIDE 66   // fp32 gates tile row stride (2 mod 32: mild conflicts, float2-aligned)

// ---- persistent device scratch ----
__device__ __align__(16) __nv_bfloat16 g_w_hi[LL*GG*KTOT];
__device__ __align__(16) __nv_bfloat16 g_w_lo[LL*GG*KTOT];
__device__ __align__(16) __nv_bfloat16 g_wo_hi[(size_t)VV*HH];
__device__ __align__(16) __nv_bfloat16 g_wo_lo[(size_t)VV*HH];
__device__ __align__(16) __nv_bfloat16 g_e_hi[(size_t)SSTEPS*BB*HH];
__device__ __align__(16) __nv_bfloat16 g_e_lo[(size_t)SSTEPS*BB*HH];
__device__ __align__(16) __nv_bfloat16 g_h_hi[2*LL*BB*HH];
__device__ __align__(16) __nv_bfloat16 g_h_lo[2*LL*BB*HH];
__device__ float    g_c[(size_t)LL*BB*HH];
__device__ unsigned g_bar_count;
__device__ unsigned g_bar_gen;

// ================= helpers =================
#define SWZ128(o) ((o) ^ (((o) >> 3) & 0x70))

__device__ __forceinline__ uint32_t smem_u32(const void* p) {
    uint32_t a;
    asm("{ .reg .u64 t; cvta.to.shared.u64 t, %1; cvt.u32.u64 %0, t; }" : "=r"(a) : "l"(p));
    return a;
}
__device__ __forceinline__ void cp16(uint32_t d, const void* s) {
    asm volatile("cp.async.cg.shared.global [%0], [%1], 16;" :: "r"(d), "l"(s));
}
__device__ __forceinline__ void cp_commit() { asm volatile("cp.async.commit_group;" ::: "memory"); }
__device__ __forceinline__ void cp_wait1()  { asm volatile("cp.async.wait_group 1;" ::: "memory"); }
__device__ __forceinline__ void cp_wait0()  { asm volatile("cp.async.wait_group 0;" ::: "memory"); }

__device__ __forceinline__ void ldsm4(uint32_t* r, uint32_t a) {
    asm volatile("ldmatrix.sync.aligned.m8n8.x4.shared.b16 {%0,%1,%2,%3}, [%4];"
        : "=r"(r[0]), "=r"(r[1]), "=r"(r[2]), "=r"(r[3]) : "r"(a));
}
__device__ __forceinline__ void mma16816(float* d, const uint32_t* a, const uint32_t* b) {
    asm volatile("mma.sync.aligned.m16n8k16.row.col.f32.bf16.bf16.f32 "
        "{%0,%1,%2,%3}, {%4,%5,%6,%7}, {%8,%9}, {%0,%1,%2,%3};"
        : "+f"(d[0]), "+f"(d[1]), "+f"(d[2]), "+f"(d[3])
        : "r"(a[0]), "r"(a[1]), "r"(a[2]), "r"(a[3]), "r"(b[0]), "r"(b[1]));
}

__device__ __forceinline__ float sigf(float v)   { return 1.0f / (1.0f + __expf(-v)); }
__device__ __forceinline__ float tanhft(float v) { return 2.0f / (1.0f + __expf(-2.0f * v)) - 1.0f; }

__device__ __forceinline__ void grid_sync() {
    __syncthreads();
    if (threadIdx.x == 0) {
        __threadfence();
        unsigned gen = *((volatile unsigned*)&g_bar_gen);
        if (atomicAdd(&g_bar_count, 1u) == NCTA - 1u) {
            atomicExch(&g_bar_count, 0u);
            __threadfence();
            atomicAdd(&g_bar_gen, 1u);
        } else {
            while (*((volatile unsigned*)&g_bar_gen) == gen) { __nanosleep(32); }
        }
        __threadfence();
    }
    __syncthreads();
}

// cp.async one chunk: A 128x64 bf16 (hi,lo) + W 64x64 bf16 (hi,lo), SW128 swizzled
__device__ __forceinline__ void issue_chunk(uint32_t tb,
    const __nv_bfloat16* ah, const __nv_bfloat16* al,
    const __nv_bfloat16* wh, const __nv_bfloat16* wl, int wstride, int tid)
{
    #pragma unroll
    for (int j = 0; j < 4; ++j) {
        int g = tid + 256 * j, m = g >> 3, q = g & 7;
        uint32_t so = SWZ128((uint32_t)(m * 128 + q * 16));
        cp16(tb + OFF_AH + so, ah + (size_t)m * HH + q * 8);
        cp16(tb + OFF_AL + so, al + (size_t)m * HH + q * 8);
    }
    #pragma unroll
    for (int j = 0; j < 2; ++j) {
        int g = tid + 256 * j, n = g >> 3, q = g & 7;
        uint32_t so = SWZ128((uint32_t)(n * 128 + q * 16));
        cp16(tb + OFF_WH + so, wh + (size_t)n * wstride + q * 8);
        cp16(tb + OFF_WL + so, wl + (size_t)n * wstride + q * 8);
    }
    cp_commit();
}

// pipelined split-bf16 HMMA GEMM: D(128x64) = sum over nch chunks, 3 split terms.
// Warp layout: wm = wid&3 (m0 = wm*32), wn = wid>>2 (n0 = wn*32); warp tile 32x32.
// d[mi][ni][4] accumulators for m-frag mi (16 rows) x n-frag ni (8 cols).
__device__ void gemm_mma(float d[2][4][4], uint32_t sb, int tid, int nch, int na0,
    const __nv_bfloat16* a0h, const __nv_bfloat16* a0l,
    const __nv_bfloat16* a1h, const __nv_bfloat16* a1l,
    const __nv_bfloat16* wh,  const __nv_bfloat16* wl, int wstride)
{
    const int wid = tid >> 5, lane = tid & 31;
    const int wm = wid & 3, wn = wid >> 2;
    // ldmatrix lane-address components (SW128 decomposed: r*128 + (kb ^ ((r&7)<<4)))
    const int mask = (lane & 7) << 4;
    const int a_row = ((lane >> 3) & 1) * 8 + (lane & 7);
    const int a_kb  = ((lane >> 4) & 1) * 16;
    const int b_row = ((lane >> 4) & 1) * 8 + (lane & 7);
    const int b_kb  = ((lane >> 3) & 1) * 16;
    uint32_t arow128[2], brow128[2];
    #pragma unroll
    for (int i = 0; i < 2; ++i) {
        arow128[i] = (uint32_t)((wm * 32 + i * 16 + a_row) * 128);
        brow128[i] = (uint32_t)((wn * 32 + i * 16 + b_row) * 128);
    }

    #pragma unroll
    for (int mi = 0; mi < 2; ++mi)
        #pragma unroll
        for (int ni = 0; ni < 4; ++ni)
            #pragma unroll
            for (int r = 0; r < 4; ++r) d[mi][ni][r] = 0.0f;

    issue_chunk(sb + SM_TBASE, a0h, a0l, wh, wl, wstride, tid);
    #pragma unroll 1
    for (int c = 0; c < nch; ++c) {
        if (c + 1 < nch) {
            const int c2 = c + 1;
            const __nv_bfloat16* ah = (c2 < na0) ? a0h + c2 * KC : a1h + (c2 - na0) * KC;
            const __nv_bfloat16* al = (c2 < na0) ? a0l + c2 * KC : a1l + (c2 - na0) * KC;
            issue_chunk(sb + SM_TBASE + ((c2 & 1) * SM_BUF), ah, al,
                        wh + c2 * KC, wl + c2 * KC, wstride, tid);
            cp_wait1();
        } else {
            cp_wait0();
        }
        __syncthreads();   // chunk c resident for all warps
        const uint32_t tb = sb + SM_TBASE + (c & 1) * SM_BUF;
        #pragma unroll
        for (int s = 0; s < 4; ++s) {
            uint32_t ah_[2][4], al_[2][4], wh_[2][4], wl_[2][4];
            const uint32_t akx = (uint32_t)((32 * s + a_kb) ^ mask);
            const uint32_t bkx = (uint32_t)((32 * s + b_kb) ^ mask);
            #pragma unroll
            for (int mi = 0; mi < 2; ++mi) {
                ldsm4(ah_[mi], tb + OFF_AH + arow128[mi] + akx);
                ldsm4(al_[mi], tb + OFF_AL + arow128[mi] + akx);
            }
            #pragma unroll
            for (int nj = 0; nj < 2; ++nj) {
                ldsm4(wh_[nj], tb + OFF_WH + brow128[nj] + bkx);
                ldsm4(wl_[nj], tb + OFF_WL + brow128[nj] + bkx);
            }
            #pragma unroll
            for (int mi = 0; mi < 2; ++mi)
                #pragma unroll
                for (int nj = 0; nj < 2; ++nj)
                    #pragma unroll
                    for (int h = 0; h < 2; ++h) {
                        float* dd = d[mi][nj * 2 + h];
                        mma16816(dd, ah_[mi], &wh_[nj][h * 2]);  // hi*hi
                        mma16816(dd, ah_[mi], &wl_[nj][h * 2]);  // hi*lo
                        mma16816(dd, al_[mi], &wh_[nj][h * 2]);  // lo*hi
                    }
        }
        __syncthreads();   // all reads done before buf reuse next iter
    }
}

// store warp accumulators into padded fp32 gates tile gs[128][GS_STRIDE]
__device__ __forceinline__ void store_gates(float* gs, const float d[2][4][4], int tid) {
    const int wid = tid >> 5, lane = tid & 31;
    const int wm = wid & 3, wn = wid >> 2;
    const int trow = wm * 32 + (lane >> 2);
    const int tcol = wn * 32 + (lane & 3) * 2;
    #pragma unroll
    for (int mi = 0; mi < 2; ++mi)
        #pragma unroll
        for (int ni = 0; ni < 4; ++ni) {
            const int r0 = trow + mi * 16, cc = tcol + ni * 8;
            *(float2*)(gs + r0 * GS_STRIDE + cc)       = make_float2(d[mi][ni][0], d[mi][ni][1]);
            *(float2*)(gs + (r0 + 8) * GS_STRIDE + cc) = make_float2(d[mi][ni][2], d[mi][ni][3]);
        }
}

// ================= prep kernels =================
__global__ void prep_w(const float* __restrict__ Wih, const float* __restrict__ Whh) {
    for (int idx = blockIdx.x * blockDim.x + threadIdx.x; idx < LL * GG * KTOT; idx += gridDim.x * blockDim.x) {
        int k = idx & 1023, n = (idx >> 10) & 2047, l = idx >> 21;
        int unit = ((n >> 6) << 4) | ((n >> 2) & 15);   // gate-interleaved permute
        int gate = n & 3;
        int src = gate * HH + unit;
        float v = (k < HH) ? Wih[((size_t)l * GG + src) * HH + k]
                           : Whh[((size_t)l * GG + src) * HH + (k - HH)];
        __nv_bfloat16 hi = __float2bfloat16(v);
        g_w_hi[idx] = hi;
        g_w_lo[idx] = __float2bfloat16(v - __bfloat162float(hi));
    }
}
__global__ void prep_wo(const float* __restrict__ Wout) {
    for (size_t idx = blockIdx.x * blockDim.x + threadIdx.x; idx < (size_t)VV * HH; idx += (size_t)gridDim.x * blockDim.x) {
        float v = Wout[idx];
        __nv_bfloat16 hi = __float2bfloat16(v);
        g_wo_hi[idx] = hi;
        g_wo_lo[idx] = __float2bfloat16(v - __bfloat162float(hi));
    }
}
__global__ void prep_e(const int* __restrict__ x, const float* __restrict__ emb) {
    for (int idx = blockIdx.x * blockDim.x + threadIdx.x; idx < SSTEPS * BB * HH; idx += gridDim.x * blockDim.x) {
        int k = idx & 511, b = (idx >> 9) & 255, t = idx >> 17;
        int tok = x[t * BB + b];   // torch .view(S,B,-1) reinterpretation
        float v = emb[(size_t)tok * HH + k];
        __nv_bfloat16 hi = __float2bfloat16(v);
        g_e_hi[idx] = hi;
        g_e_lo[idx] = __float2bfloat16(v - __bfloat162float(hi));
    }
}

// ================= main persistent kernel =================
__global__ void __launch_bounds__(NTHR, 1)
lstm_mma(const float* __restrict__ h0, const float* __restrict__ c0,
         const float* __restrict__ bih, const float* __restrict__ bhh,
         const float* __restrict__ bout, float* __restrict__ out)
{
    extern __shared__ __align__(1024) char smem[];
    const uint32_t sb = smem_u32(smem);
    const int tid = threadIdx.x, bid = blockIdx.x;
    const int mb = bid >> 5;          // batch half (128 rows)
    const int nb = bid & 31;          // N tile (64 gate cols = 16 units)

    float* bias_s = (float*)(smem + SM_BIAS);
    float* gs     = (float*)(smem + SM_TBASE);

    for (int j = tid; j < LL * 64; j += NTHR) {
        int l = j >> 6, nl = j & 63;
        int gi = l * GG + (nl & 3) * HH + nb * 16 + (nl >> 2);
        bias_s[j] = bih[gi] + bhh[gi];
    }
    // c slice (CTA-private) and h0 split (cooperative)
    for (int j = tid; j < LL * 128 * 16; j += NTHR) {
        int l = j >> 11, m = (j >> 4) & 127, u = j & 15;
        size_t idx = ((size_t)l * BB + mb * 128 + m) * HH + nb * 16 + u;
        g_c[idx] = c0[idx];
    }
    for (int i = bid * NTHR + tid; i < LL * BB * HH; i += NCTA * NTHR) {
        float v = h0[i];
        __nv_bfloat16 hi = __float2bfloat16(v);
        g_h_hi[LL * BB * HH + i] = hi;
        g_h_lo[LL * BB * HH + i] = __float2bfloat16(v - __bfloat162float(hi));
    }
    grid_sync();

    const size_t row0 = (size_t)(mb * 128) * HH;
    float d[2][4][4];

    #pragma unroll 1
    for (int t = 0; t < SSTEPS; ++t) {
        const int cur = t & 1, prev = cur ^ 1;
        #pragma unroll 1
        for (int l = 0; l < LL; ++l) {
            const __nv_bfloat16 *a0h, *a0l;
            if (l == 0) {
                a0h = g_e_hi + (size_t)t * BB * HH + row0;
                a0l = g_e_lo + (size_t)t * BB * HH + row0;
            } else {
                size_t o = ((size_t)cur * LL + (l - 1)) * BB * HH + row0;
                a0h = g_h_hi + o; a0l = g_h_lo + o;
            }
            const size_t o1 = ((size_t)prev * LL + l) * BB * HH + row0;
            const __nv_bfloat16* wbh = g_w_hi + ((size_t)l * GG + nb * 64) * KTOT;
            const __nv_bfloat16* wbl = g_w_lo + ((size_t)l * GG + nb * 64) * KTOT;

            gemm_mma(d, sb, tid, NCH, 8,
                     a0h, a0l, g_h_hi + o1, g_h_lo + o1, wbh, wbl, KTOT);

            store_gates(gs, d, tid);
            __syncthreads();

            if (tid < 128) {   // activation: 128 threads = 128 batch rows, 16 units each
                const int b = mb * 128 + tid;
                const float* gr = gs + tid * GS_STRIDE;
                float* cptr = g_c + ((size_t)l * BB + b) * HH + nb * 16;
                const size_t ho = ((size_t)cur * LL + l) * BB * HH + (size_t)b * HH + nb * 16;
                #pragma unroll
                for (int u = 0; u < 16; ++u) {
                    const float gi = gr[4*u+0] + bias_s[l*64 + 4*u+0];
                    const float gf = gr[4*u+1] + bias_s[l*64 + 4*u+1];
                    const float gg = gr[4*u+2] + bias_s[l*64 + 4*u+2];
                    const float go = gr[4*u+3] + bias_s[l*64 + 4*u+3];
                    const float cn = sigf(gf) * cptr[u] + sigf(gi) * tanhft(gg);
                    cptr[u] = cn;
                    const float hv = sigf(go) * tanhft(cn);
                    __nv_bfloat16 hi = __float2bfloat16(hv);
                    g_h_hi[ho + u] = hi;
                    g_h_lo[ho + u] = __float2bfloat16(hv - __bfloat162float(hi));
                }
            }
            grid_sync();   // h[cur][l] complete before next layer reads it
        }
    }

    // ---- output GEMM: logits 256x32000, K=512 -> 1000 tiles of 128x64 ----
    const size_t hf = ((size_t)((SSTEPS - 1) & 1) * LL + (LL - 1)) * BB * HH;
    #pragma unroll 1
    for (int tt = bid; tt < 1000; tt += NCTA) {
        const int b0 = (tt / 500) * 128;
        const int v0 = (tt % 500) * 64;
        const __nv_bfloat16* ah = g_h_hi + hf + (size_t)b0 * HH;
        const __nv_bfloat16* al = g_h_lo + hf + (size_t)b0 * HH;
        gemm_mma(d, sb, tid, NCHO, NCHO, ah, al, ah, al,
                 g_wo_hi + (size_t)v0 * HH, g_wo_lo + (size_t)v0 * HH, HH);
        store_gates(gs, d, tid);
        __syncthreads();
        if (tid < 128) {
            const float* gr = gs + tid * GS_STRIDE;
            float* op = out + (size_t)(b0 + tid) * VV + v0;
            #pragma unroll
            for (int c4 = 0; c4 < 16; ++c4) {
                float4 s;
                s.x = gr[4*c4+0] + bout[v0 + 4*c4+0];
                s.y = gr[4*c4+1] + bout[v0 + 4*c4+1];
                s.z = gr[4*c4+2] + bout[v0 + 4*c4+2];
                s.w = gr[4*c4+3] + bout[v0 + 4*c4+3];
                *(float4*)(op + 4*c4) = s;
            }
        }
        __syncthreads();   // gs free before next tile's cp.async overwrites it
    }
}

extern "C" void kernel_launch(void* const* d_in, const int* in_sizes, int n_in,
                              void* d_out, int out_size) {
    (void)in_sizes; (void)n_in; (void)out_size;
    prep_w<<<2048, 256>>>((const float*)d_in[4], (const float*)d_in[5]);
    prep_wo<<<2048, 256>>>((const float*)d_in[8]);
    prep_e<<<2048, 256>>>((const int*)d_in[0], (const float*)d_in[3]);
    cudaFuncSetAttribute(lstm_mma, cudaFuncAttributeMaxDynamicSharedMemorySize, SMEM_TOTAL);
    lstm_mma<<<NCTA, NTHR, SMEM_TOTAL>>>(
        (const float*)d_in[1],   // h0
        (const float*)d_in[2],   // c0
        (const float*)d_in[6],   // b_ih
        (const float*)d_in[7],   // b_hh
        (const float*)d_in[9],   // b_out
        (float*)d_out);
}

// round 9
// speedup vs baseline: 4.2036x; 1.5665x over previous
#include <cuda_runtime.h>
#include <cuda_bf16.h>
#include <math.h>
#include <stdint.h>

#define LL 5
#define BB 256
#define HH 512
#define GG 2048
#define SSTEPS 128
#define VV 32000
#define KTOT 1024

#define NCTA 128
#define NTHR 256
#define KC 64          // k elems per chunk (64 bf16 = 128B row = SW128 atom)
#define NCHL 8         // chunks per half-K layer GEMM (K=512 per CTA)
#define NCHO 8         // chunks per output GEMM (K=512)

// dynamic SMEM layout (bytes)
#define SM_BIAS  128   // 5*64 floats
#define SM_TBASE 2048
#define SM_BUF   49152 // A_hi 16K | A_lo 16K | W_hi 8K | W_lo 8K
#define OFF_AH 0
#define OFF_AL 16384
#define OFF_WH 32768
#define OFF_WL 40960
#define SMEM_TOTAL (SM_TBASE + 2*SM_BUF)   // 100352
#define GS_STRIDE 66   // fp32 gates tile row stride (gs overlays buffer 0 after gemm)

// ---- persistent device scratch ----
__device__ __align__(16) __nv_bfloat16 g_w_hi[LL*GG*KTOT];
__device__ __align__(16) __nv_bfloat16 g_w_lo[LL*GG*KTOT];
__device__ __align__(16) __nv_bfloat16 g_wo_hi[(size_t)VV*HH];
__device__ __align__(16) __nv_bfloat16 g_wo_lo[(size_t)VV*HH];
__device__ __align__(16) __nv_bfloat16 g_e_hi[(size_t)SSTEPS*BB*HH];
__device__ __align__(16) __nv_bfloat16 g_e_lo[(size_t)SSTEPS*BB*HH];
__device__ __align__(16) __nv_bfloat16 g_h_hi[2*LL*BB*HH];
__device__ __align__(16) __nv_bfloat16 g_h_lo[2*LL*BB*HH];
__device__ float    g_c[(size_t)LL*BB*HH];
__device__ __align__(16) float g_part[2*2*32*NTHR*32];   // [kh][mq][nb][tid*32]
__device__ unsigned g_pairflag[2*32];                    // [mq][nb]
__device__ unsigned g_bar_count;
__device__ unsigned g_bar_gen;

// ================= helpers =================
#define SWZ128(o) ((o) ^ (((o) >> 3) & 0x70))

__device__ __forceinline__ uint32_t smem_u32(const void* p) {
    uint32_t a;
    asm("{ .reg .u64 t; cvta.to.shared.u64 t, %1; cvt.u32.u64 %0, t; }" : "=r"(a) : "l"(p));
    return a;
}
__device__ __forceinline__ void cp16(uint32_t d, const void* s) {
    asm volatile("cp.async.cg.shared.global [%0], [%1], 16;" :: "r"(d), "l"(s));
}
__device__ __forceinline__ void cp_commit() { asm volatile("cp.async.commit_group;" ::: "memory"); }
__device__ __forceinline__ void cp_wait1()  { asm volatile("cp.async.wait_group 1;" ::: "memory"); }
__device__ __forceinline__ void cp_wait0()  { asm volatile("cp.async.wait_group 0;" ::: "memory"); }

__device__ __forceinline__ void ldsm4(uint32_t* r, uint32_t a) {
    asm volatile("ldmatrix.sync.aligned.m8n8.x4.shared.b16 {%0,%1,%2,%3}, [%4];"
        : "=r"(r[0]), "=r"(r[1]), "=r"(r[2]), "=r"(r[3]) : "r"(a));
}
__device__ __forceinline__ void mma16816(float* d, const uint32_t* a, const uint32_t* b) {
    asm volatile("mma.sync.aligned.m16n8k16.row.col.f32.bf16.bf16.f32 "
        "{%0,%1,%2,%3}, {%4,%5,%6,%7}, {%8,%9}, {%0,%1,%2,%3};"
        : "+f"(d[0]), "+f"(d[1]), "+f"(d[2]), "+f"(d[3])
        : "r"(a[0]), "r"(a[1]), "r"(a[2]), "r"(a[3]), "r"(b[0]), "r"(b[1]));
}
// L2-coherent float4 load (bypasses L1 -> always sees partner CTA's STGs)
__device__ __forceinline__ float4 ldcg4(const float* p) {
    float4 v;
    asm volatile("ld.global.cg.v4.f32 {%0,%1,%2,%3}, [%4];"
        : "=f"(v.x), "=f"(v.y), "=f"(v.z), "=f"(v.w) : "l"(p));
    return v;
}

__device__ __forceinline__ float sigf(float v)   { return 1.0f / (1.0f + __expf(-v)); }
__device__ __forceinline__ float tanhft(float v) { return 2.0f / (1.0f + __expf(-2.0f * v)) - 1.0f; }

__device__ __forceinline__ void grid_sync() {
    __syncthreads();
    if (threadIdx.x == 0) {
        __threadfence();
        unsigned gen = *((volatile unsigned*)&g_bar_gen);
        if (atomicAdd(&g_bar_count, 1u) == NCTA - 1u) {
            atomicExch(&g_bar_count, 0u);
            __threadfence();
            atomicAdd(&g_bar_gen, 1u);
        } else {
            while (*((volatile unsigned*)&g_bar_gen) == gen) { __nanosleep(32); }
        }
        __threadfence();
    }
    __syncthreads();
}

// cp.async one chunk: A 128x64 bf16 (hi,lo) + W 64x64 bf16 (hi,lo), SW128 swizzled
__device__ __forceinline__ void issue_chunk(uint32_t tb,
    const __nv_bfloat16* ah, const __nv_bfloat16* al,
    const __nv_bfloat16* wh, const __nv_bfloat16* wl, int wstride, int tid)
{
    #pragma unroll
    for (int j = 0; j < 4; ++j) {
        int g = tid + 256 * j, m = g >> 3, q = g & 7;
        uint32_t so = SWZ128((uint32_t)(m * 128 + q * 16));
        cp16(tb + OFF_AH + so, ah + (size_t)m * HH + q * 8);
        cp16(tb + OFF_AL + so, al + (size_t)m * HH + q * 8);
    }
    #pragma unroll
    for (int j = 0; j < 2; ++j) {
        int g = tid + 256 * j, n = g >> 3, q = g & 7;
        uint32_t so = SWZ128((uint32_t)(n * 128 + q * 16));
        cp16(tb + OFF_WH + so, wh + (size_t)n * wstride + q * 8);
        cp16(tb + OFF_WL + so, wl + (size_t)n * wstride + q * 8);
    }
    cp_commit();
}

// pipelined split-bf16 HMMA GEMM over a SINGLE contiguous A source.
// D(128x64) accumulated in regs; 8 warps = 4m x 2n, warp tile 32x32.
// MMA issued term-major (8 independent accums between reuses of each).
__device__ void gemm_mma(float d[2][4][4], uint32_t sb, int tid, int nch,
    const __nv_bfloat16* ah0, const __nv_bfloat16* al0,
    const __nv_bfloat16* wh,  const __nv_bfloat16* wl, int wstride)
{
    const int wid = tid >> 5, lane = tid & 31;
    const int wm = wid & 3, wn = wid >> 2;
    const int mask = (lane & 7) << 4;
    const int a_row = ((lane >> 3) & 1) * 8 + (lane & 7);
    const int a_kb  = ((lane >> 4) & 1) * 16;
    const int b_row = ((lane >> 4) & 1) * 8 + (lane & 7);
    const int b_kb  = ((lane >> 3) & 1) * 16;
    uint32_t arow128[2], brow128[2];
    #pragma unroll
    for (int i = 0; i < 2; ++i) {
        arow128[i] = (uint32_t)((wm * 32 + i * 16 + a_row) * 128);
        brow128[i] = (uint32_t)((wn * 32 + i * 16 + b_row) * 128);
    }

    #pragma unroll
    for (int mi = 0; mi < 2; ++mi)
        #pragma unroll
        for (int ni = 0; ni < 4; ++ni)
            #pragma unroll
            for (int r = 0; r < 4; ++r) d[mi][ni][r] = 0.0f;

    issue_chunk(sb + SM_TBASE, ah0, al0, wh, wl, wstride, tid);
    #pragma unroll 1
    for (int c = 0; c < nch; ++c) {
        if (c + 1 < nch) {
            const int c2 = c + 1;
            issue_chunk(sb + SM_TBASE + ((c2 & 1) * SM_BUF), ah0 + c2 * KC, al0 + c2 * KC,
                        wh + c2 * KC, wl + c2 * KC, wstride, tid);
            cp_wait1();
        } else {
            cp_wait0();
        }
        __syncthreads();
        const uint32_t tb = sb + SM_TBASE + (c & 1) * SM_BUF;
        #pragma unroll
        for (int s = 0; s < 4; ++s) {
            uint32_t ah_[2][4], al_[2][4], wh_[2][4], wl_[2][4];
            const uint32_t akx = (uint32_t)((32 * s + a_kb) ^ mask);
            const uint32_t bkx = (uint32_t)((32 * s + b_kb) ^ mask);
            #pragma unroll
            for (int mi = 0; mi < 2; ++mi) {
                ldsm4(ah_[mi], tb + OFF_AH + arow128[mi] + akx);
                ldsm4(al_[mi], tb + OFF_AL + arow128[mi] + akx);
            }
            #pragma unroll
            for (int nj = 0; nj < 2; ++nj) {
                ldsm4(wh_[nj], tb + OFF_WH + brow128[nj] + bkx);
                ldsm4(wl_[nj], tb + OFF_WL + brow128[nj] + bkx);
            }
            // term-major: 8 independent accumulators between reuses
            #pragma unroll
            for (int mi = 0; mi < 2; ++mi)
                #pragma unroll
                for (int nj = 0; nj < 2; ++nj)
                    #pragma unroll
                    for (int h = 0; h < 2; ++h)
                        mma16816(d[mi][nj * 2 + h], ah_[mi], &wh_[nj][h * 2]);
            #pragma unroll
            for (int mi = 0; mi < 2; ++mi)
                #pragma unroll
                for (int nj = 0; nj < 2; ++nj)
                    #pragma unroll
                    for (int h = 0; h < 2; ++h)
                        mma16816(d[mi][nj * 2 + h], ah_[mi], &wl_[nj][h * 2]);
            #pragma unroll
            for (int mi = 0; mi < 2; ++mi)
                #pragma unroll
                for (int nj = 0; nj < 2; ++nj)
                    #pragma unroll
                    for (int h = 0; h < 2; ++h)
                        mma16816(d[mi][nj * 2 + h], al_[mi], &wh_[nj][h * 2]);
        }
        __syncthreads();
    }
}

// store warp accumulators into padded fp32 gates tile gs[128][GS_STRIDE]
__device__ __forceinline__ void store_gates(float* gs, const float d[2][4][4], int tid) {
    const int wid = tid >> 5, lane = tid & 31;
    const int wm = wid & 3, wn = wid >> 2;
    const int trow = wm * 32 + (lane >> 2);
    const int tcol = wn * 32 + (lane & 3) * 2;
    #pragma unroll
    for (int mi = 0; mi < 2; ++mi)
        #pragma unroll
        for (int ni = 0; ni < 4; ++ni) {
            const int r0 = trow + mi * 16, cc = tcol + ni * 8;
            *(float2*)(gs + r0 * GS_STRIDE + cc)       = make_float2(d[mi][ni][0], d[mi][ni][1]);
            *(float2*)(gs + (r0 + 8) * GS_STRIDE + cc) = make_float2(d[mi][ni][2], d[mi][ni][3]);
        }
}

// ================= prep kernels =================
__global__ void prep_w(const float* __restrict__ Wih, const float* __restrict__ Whh) {
    for (int idx = blockIdx.x * blockDim.x + threadIdx.x; idx < LL * GG * KTOT; idx += gridDim.x * blockDim.x) {
        int k = idx & 1023, n = (idx >> 10) & 2047, l = idx >> 21;
        int unit = ((n >> 6) << 4) | ((n >> 2) & 15);   // gate-interleaved permute
        int gate = n & 3;
        int src = gate * HH + unit;
        float v = (k < HH) ? Wih[((size_t)l * GG + src) * HH + k]
                           : Whh[((size_t)l * GG + src) * HH + (k - HH)];
        __nv_bfloat16 hi = __float2bfloat16(v);
        g_w_hi[idx] = hi;
        g_w_lo[idx] = __float2bfloat16(v - __bfloat162float(hi));
    }
}
__global__ void prep_wo(const float* __restrict__ Wout) {
    for (size_t idx = blockIdx.x * blockDim.x + threadIdx.x; idx < (size_t)VV * HH; idx += (size_t)gridDim.x * blockDim.x) {
        float v = Wout[idx];
        __nv_bfloat16 hi = __float2bfloat16(v);
        g_wo_hi[idx] = hi;
        g_wo_lo[idx] = __float2bfloat16(v - __bfloat162float(hi));
    }
}
__global__ void prep_e(const int* __restrict__ x, const float* __restrict__ emb) {
    for (int idx = blockIdx.x * blockDim.x + threadIdx.x; idx < SSTEPS * BB * HH; idx += gridDim.x * blockDim.x) {
        int k = idx & 511, b = (idx >> 9) & 255, t = idx >> 17;
        int tok = x[t * BB + b];   // torch .view(S,B,-1) reinterpretation
        float v = emb[(size_t)tok * HH + k];
        __nv_bfloat16 hi = __float2bfloat16(v);
        g_e_hi[idx] = hi;
        g_e_lo[idx] = __float2bfloat16(v - __bfloat162float(hi));
    }
}

// ================= main persistent kernel =================
__global__ void __launch_bounds__(NTHR, 1)
lstm_mma(const float* __restrict__ h0, const float* __restrict__ c0,
         const float* __restrict__ bih, const float* __restrict__ bhh,
         const float* __restrict__ bout, float* __restrict__ out)
{
    extern __shared__ __align__(1024) char smem[];
    const uint32_t sb = smem_u32(smem);
    const int tid = threadIdx.x, bid = blockIdx.x;
    const int kh = bid & 1;           // K half
    const int nb = (bid >> 1) & 31;   // N tile (64 gate cols = 16 units)
    const int mq = bid >> 6;          // batch half (128 rows)

    float* bias_s = (float*)(smem + SM_BIAS);
    float* gs     = (float*)(smem + SM_TBASE);   // overlays buffer 0 (dead after gemm)

    for (int j = tid; j < LL * 64; j += NTHR) {
        int l = j >> 6, nl = j & 63;
        int gi = l * GG + (nl & 3) * HH + nb * 16 + (nl >> 2);
        bias_s[j] = bih[gi] + bhh[gi];
    }
    // c slice init: this CTA owns rows [mq*128 + kh*64, +64), units [nb*16, +16)
    for (int j = tid; j < LL * 64 * 16; j += NTHR) {
        int l = j >> 10, r = (j >> 4) & 63, u = j & 15;
        size_t idx = ((size_t)l * BB + mq * 128 + kh * 64 + r) * HH + nb * 16 + u;
        g_c[idx] = c0[idx];
    }
    // h0 split (cooperative)
    for (int i = bid * NTHR + tid; i < LL * BB * HH; i += NCTA * NTHR) {
        float v = h0[i];
        __nv_bfloat16 hi = __float2bfloat16(v);
        g_h_hi[LL * BB * HH + i] = hi;
        g_h_lo[LL * BB * HH + i] = __float2bfloat16(v - __bfloat162float(hi));
    }
    if (kh == 0 && tid == 0) atomicExch(&g_pairflag[mq * 32 + nb], 0u);  // replay-safe reset
    grid_sync();

    const size_t row0 = (size_t)(mq * 128) * HH;
    float d[2][4][4];
    float* mypart       = g_part + ((size_t)((kh * 2 + mq) * 32 + nb) * NTHR + tid) * 32;
    const float* thpart = g_part + ((size_t)(((kh ^ 1) * 2 + mq) * 32 + nb) * NTHR + tid) * 32;
    unsigned* pflag = &g_pairflag[mq * 32 + nb];
    unsigned pair_exp = 0;

    #pragma unroll 1
    for (int t = 0; t < SSTEPS; ++t) {
        const int cur = t & 1, prev = cur ^ 1;
        #pragma unroll 1
        for (int l = 0; l < LL; ++l) {
            // kh=0: input half of K (emb or h of layer below, k 0..511)
            // kh=1: recurrent half (h_prev of this layer, k 512..1023)
            const __nv_bfloat16 *ah0, *al0;
            if (kh == 0) {
                if (l == 0) {
                    ah0 = g_e_hi + (size_t)t * BB * HH + row0;
                    al0 = g_e_lo + (size_t)t * BB * HH + row0;
                } else {
                    size_t o = ((size_t)cur * LL + (l - 1)) * BB * HH + row0;
                    ah0 = g_h_hi + o; al0 = g_h_lo + o;
                }
            } else {
                size_t o = ((size_t)prev * LL + l) * BB * HH + row0;
                ah0 = g_h_hi + o; al0 = g_h_lo + o;
            }
            const __nv_bfloat16* wbh = g_w_hi + ((size_t)l * GG + nb * 64) * KTOT + kh * (NCHL * KC);
            const __nv_bfloat16* wbl = g_w_lo + ((size_t)l * GG + nb * 64) * KTOT + kh * (NCHL * KC);

            gemm_mma(d, sb, tid, NCHL, ah0, al0, wbh, wbl, KTOT);

            // ---- pair exchange: my partial -> gmem; add partner's (L2-coherent) ----
            #pragma unroll
            for (int mi = 0; mi < 2; ++mi)
                #pragma unroll
                for (int ni = 0; ni < 4; ++ni)
                    *(float4*)(mypart + (mi * 4 + ni) * 4) = *(const float4*)d[mi][ni];
            __threadfence();           // my STGs visible at L2 before flag
            __syncthreads();
            if (tid == 0) atomicAdd(pflag, 1u);
            pair_exp += 2;
            if (tid == 0) {
                while (*((volatile unsigned*)pflag) < pair_exp) { __nanosleep(20); }
            }
            __syncthreads();
            #pragma unroll
            for (int mi = 0; mi < 2; ++mi)
                #pragma unroll
                for (int ni = 0; ni < 4; ++ni) {
                    const float4 p = ldcg4(thpart + (mi * 4 + ni) * 4);
                    d[mi][ni][0] += p.x; d[mi][ni][1] += p.y;
                    d[mi][ni][2] += p.z; d[mi][ni][3] += p.w;
                }

            store_gates(gs, d, tid);
            __syncthreads();

            // activation: this CTA handles its 64-row half (1024 items, 4/thread)
            #pragma unroll
            for (int i = 0; i < 4; ++i) {
                const int j = tid + NTHR * i;
                const int r = j >> 4, u = j & 15;
                const int row = kh * 64 + r;
                const float* gr = gs + row * GS_STRIDE + 4 * u;
                const int b = mq * 128 + row;
                const float gi = gr[0] + bias_s[l * 64 + 4 * u + 0];
                const float gf = gr[1] + bias_s[l * 64 + 4 * u + 1];
                const float gg = gr[2] + bias_s[l * 64 + 4 * u + 2];
                const float go = gr[3] + bias_s[l * 64 + 4 * u + 3];
                const size_t ci = ((size_t)l * BB + b) * HH + nb * 16 + u;
                const float cn = sigf(gf) * g_c[ci] + sigf(gi) * tanhft(gg);
                g_c[ci] = cn;
                const float hv = sigf(go) * tanhft(cn);
                const size_t ho = ((size_t)cur * LL + l) * BB * HH + (size_t)b * HH + nb * 16 + u;
                __nv_bfloat16 hi = __float2bfloat16(hv);
                g_h_hi[ho] = hi;
                g_h_lo[ho] = __float2bfloat16(hv - __bfloat162float(hi));
            }
            grid_sync();   // h[cur][l] complete before next layer reads it
        }
    }

    // ---- output GEMM: logits 256x32000, K=512 -> 2 x 500 = 1000 tiles of 128x64 ----
    const size_t hf = ((size_t)((SSTEPS - 1) & 1) * LL + (LL - 1)) * BB * HH;
    #pragma unroll 1
    for (int tt = bid; tt < 1000; tt += NCTA) {
        const int b0 = (tt / 500) * 128;
        const int v0 = (tt % 500) * 64;
        gemm_mma(d, sb, tid, NCHO,
                 g_h_hi + hf + (size_t)b0 * HH, g_h_lo + hf + (size_t)b0 * HH,
                 g_wo_hi + (size_t)v0 * HH, g_wo_lo + (size_t)v0 * HH, HH);
        store_gates(gs, d, tid);
        __syncthreads();
        if (tid < 128) {
            const float* gr = gs + tid * GS_STRIDE;
            float* op = out + (size_t)(b0 + tid) * VV + v0;
            #pragma unroll
            for (int c4 = 0; c4 < 16; ++c4) {
                float4 s;
                s.x = gr[4*c4+0] + bout[v0 + 4*c4+0];
                s.y = gr[4*c4+1] + bout[v0 + 4*c4+1];
                s.z = gr[4*c4+2] + bout[v0 + 4*c4+2];
                s.w = gr[4*c4+3] + bout[v0 + 4*c4+3];
                *(float4*)(op + 4*c4) = s;
            }
        }
        __syncthreads();   // gs free before next tile's cp.async overwrites it
    }
}

extern "C" void kernel_launch(void* const* d_in, const int* in_sizes, int n_in,
                              void* d_out, int out_size) {
    (void)in_sizes; (void)n_in; (void)out_size;
    prep_w<<<2048, 256>>>((const float*)d_in[4], (const float*)d_in[5]);
    prep_wo<<<2048, 256>>>((const float*)d_in[8]);
    prep_e<<<2048, 256>>>((const int*)d_in[0], (const float*)d_in[3]);
    cudaFuncSetAttribute(lstm_mma, cudaFuncAttributeMaxDynamicSharedMemorySize, SMEM_TOTAL);
    lstm_mma<<<NCTA, NTHR, SMEM_TOTAL>>>(
        (const float*)d_in[1],   // h0
        (const float*)d_in[2],   // c0
        (const float*)d_in[6],   // b_ih
        (const float*)d_in[7],   // b_hh
        (const float*)d_in[9],   // b_out
        (float*)d_out);
}

// round 11
// speedup vs baseline: 4.5518x; 1.0828x over previous
#include <cuda_runtime.h>
#include <cuda_bf16.h>
#include <math.h>
#include <stdint.h>

#define LL 5
#define BB 256
#define HH 512
#define GG 2048
#define SSTEPS 128
#define VV 32000
#define KTOT 1024

#define NCTA 128
#define NTHR 256
#define KC 64          // k elems per chunk (64 bf16 = 128B row = SW128 atom)
#define NCHL 8         // chunks per half-K layer GEMM (K=512 per CTA)
#define NCHO 8         // chunks per output GEMM (K=512)
#define NSTG 4         // cp.async pipeline stages

// dynamic SMEM layout (bytes)
#define SM_BIAS  128   // 5*64 floats
#define SM_TBASE 2048
#define SM_BUF   49152 // A_hi 16K | A_lo 16K | W_hi 8K | W_lo 8K
#define OFF_AH 0
#define OFF_AL 16384
#define OFF_WH 32768
#define OFF_WL 40960
#define SMEM_TOTAL (SM_TBASE + NSTG*SM_BUF)   // 198656
#define GS_STRIDE 66   // fp32 gates tile row stride (gs overlays stage-0 buffer, phase-2 only)

// ---- persistent device scratch ----
__device__ __align__(16) __nv_bfloat16 g_w_hi[LL*GG*KTOT];
__device__ __align__(16) __nv_bfloat16 g_w_lo[LL*GG*KTOT];
__device__ __align__(16) __nv_bfloat16 g_wo_hi[(size_t)VV*HH];
__device__ __align__(16) __nv_bfloat16 g_wo_lo[(size_t)VV*HH];
__device__ __align__(16) __nv_bfloat16 g_e_hi[(size_t)SSTEPS*BB*HH];
__device__ __align__(16) __nv_bfloat16 g_e_lo[(size_t)SSTEPS*BB*HH];
__device__ __align__(16) __nv_bfloat16 g_h_hi[2*LL*BB*HH];
__device__ __align__(16) __nv_bfloat16 g_h_lo[2*LL*BB*HH];
__device__ float    g_c[(size_t)LL*BB*HH];
__device__ __align__(16) float g_part[2*2*32*NTHR*LL*32];  // [kh][mq][nb][tid][cell][32]
__device__ unsigned g_pairflag[2*32];                      // [mq][nb]
__device__ unsigned g_bar_count;
__device__ unsigned g_bar_gen;

// ================= helpers =================
#define SWZ128(o) ((o) ^ (((o) >> 3) & 0x70))

__device__ __forceinline__ uint32_t smem_u32(const void* p) {
    uint32_t a;
    asm("{ .reg .u64 t; cvta.to.shared.u64 t, %1; cvt.u32.u64 %0, t; }" : "=r"(a) : "l"(p));
    return a;
}
__device__ __forceinline__ void cp16(uint32_t d, const void* s) {
    asm volatile("cp.async.cg.shared.global [%0], [%1], 16;" :: "r"(d), "l"(s));
}
__device__ __forceinline__ void cp_commit() { asm volatile("cp.async.commit_group;" ::: "memory"); }
__device__ __forceinline__ void cp_wait2()  { asm volatile("cp.async.wait_group 2;" ::: "memory"); }
__device__ __forceinline__ void cp_wait1()  { asm volatile("cp.async.wait_group 1;" ::: "memory"); }
__device__ __forceinline__ void cp_wait0()  { asm volatile("cp.async.wait_group 0;" ::: "memory"); }

__device__ __forceinline__ void ldsm4(uint32_t* r, uint32_t a) {
    asm volatile("ldmatrix.sync.aligned.m8n8.x4.shared.b16 {%0,%1,%2,%3}, [%4];"
        : "=r"(r[0]), "=r"(r[1]), "=r"(r[2]), "=r"(r[3]) : "r"(a));
}
__device__ __forceinline__ void mma16816(float* d, const uint32_t* a, const uint32_t* b) {
    asm volatile("mma.sync.aligned.m16n8k16.row.col.f32.bf16.bf16.f32 "
        "{%0,%1,%2,%3}, {%4,%5,%6,%7}, {%8,%9}, {%0,%1,%2,%3};"
        : "+f"(d[0]), "+f"(d[1]), "+f"(d[2]), "+f"(d[3])
        : "r"(a[0]), "r"(a[1]), "r"(a[2]), "r"(a[3]), "r"(b[0]), "r"(b[1]));
}
// L2-coherent float4 load (bypasses L1 -> always sees partner CTA's STGs)
__device__ __forceinline__ float4 ldcg4(const float* p) {
    float4 v;
    asm volatile("ld.global.cg.v4.f32 {%0,%1,%2,%3}, [%4];"
        : "=f"(v.x), "=f"(v.y), "=f"(v.z), "=f"(v.w) : "l"(p));
    return v;
}

__device__ __forceinline__ float sigf(float v)   { return 1.0f / (1.0f + __expf(-v)); }
__device__ __forceinline__ float tanhft(float v) { return 2.0f / (1.0f + __expf(-2.0f * v)) - 1.0f; }

__device__ __forceinline__ void grid_sync() {
    __syncthreads();
    if (threadIdx.x == 0) {
        __threadfence();
        unsigned gen = *((volatile unsigned*)&g_bar_gen);
        if (atomicAdd(&g_bar_count, 1u) == NCTA - 1u) {
            atomicExch(&g_bar_count, 0u);
            __threadfence();
            atomicAdd(&g_bar_gen, 1u);
        } else {
            while (*((volatile unsigned*)&g_bar_gen) == gen) { __nanosleep(32); }
        }
        __threadfence();
    }
    __syncthreads();
}

// cp.async one chunk: A 128x64 bf16 (hi,lo) + W 64x64 bf16 (hi,lo), SW128 swizzled
__device__ __forceinline__ void issue_chunk(uint32_t tb,
    const __nv_bfloat16* ah, const __nv_bfloat16* al,
    const __nv_bfloat16* wh, const __nv_bfloat16* wl, int wstride, int tid)
{
    #pragma unroll
    for (int j = 0; j < 4; ++j) {
        int g = tid + 256 * j, m = g >> 3, q = g & 7;
        uint32_t so = SWZ128((uint32_t)(m * 128 + q * 16));
        cp16(tb + OFF_AH + so, ah + (size_t)m * HH + q * 8);
        cp16(tb + OFF_AL + so, al + (size_t)m * HH + q * 8);
    }
    #pragma unroll
    for (int j = 0; j < 2; ++j) {
        int g = tid + 256 * j, n = g >> 3, q = g & 7;
        uint32_t so = SWZ128((uint32_t)(n * 128 + q * 16));
        cp16(tb + OFF_WH + so, wh + (size_t)n * wstride + q * 8);
        cp16(tb + OFF_WL + so, wl + (size_t)n * wstride + q * 8);
    }
    cp_commit();
}

// 4-stage pipelined split-bf16 HMMA GEMM. D(128x64) in regs; 8 warps = 4m x 2n.
// One __syncthreads per chunk; buffer written at iter c+3 was last read at c-1
// (all warps past syncthreads_c => compute c-1 complete), so reuse is safe.
__device__ void gemm_mma(float d[2][4][4], uint32_t sb, int tid, int nch,
    const __nv_bfloat16* ah0, const __nv_bfloat16* al0,
    const __nv_bfloat16* wh,  const __nv_bfloat16* wl, int wstride)
{
    const int wid = tid >> 5, lane = tid & 31;
    const int wm = wid & 3, wn = wid >> 2;
    const int mask = (lane & 7) << 4;
    const int a_row = ((lane >> 3) & 1) * 8 + (lane & 7);
    const int a_kb  = ((lane >> 4) & 1) * 16;
    const int b_row = ((lane >> 4) & 1) * 8 + (lane & 7);
    const int b_kb  = ((lane >> 3) & 1) * 16;
    uint32_t arow128[2], brow128[2];
    #pragma unroll
    for (int i = 0; i < 2; ++i) {
        arow128[i] = (uint32_t)((wm * 32 + i * 16 + a_row) * 128);
        brow128[i] = (uint32_t)((wn * 32 + i * 16 + b_row) * 128);
    }

    #pragma unroll
    for (int mi = 0; mi < 2; ++mi)
        #pragma unroll
        for (int ni = 0; ni < 4; ++ni)
            #pragma unroll
            for (int r = 0; r < 4; ++r) d[mi][ni][r] = 0.0f;

    // prologue: prefetch chunks 0..2
    #pragma unroll
    for (int p = 0; p < NSTG - 1; ++p)
        if (p < nch)
            issue_chunk(sb + SM_TBASE + p * SM_BUF, ah0 + p * KC, al0 + p * KC,
                        wh + p * KC, wl + p * KC, wstride, tid);

    #pragma unroll 1
    for (int c = 0; c < nch; ++c) {
        const int rem = nch - 1 - c;             // groups allowed in flight
        if (rem >= 2) cp_wait2(); else if (rem == 1) cp_wait1(); else cp_wait0();
        __syncthreads();
        if (c + NSTG - 1 < nch) {
            const int c2 = c + NSTG - 1;
            issue_chunk(sb + SM_TBASE + (c2 & (NSTG - 1)) * SM_BUF,
                        ah0 + c2 * KC, al0 + c2 * KC,
                        wh + c2 * KC, wl + c2 * KC, wstride, tid);
        }
        const uint32_t tb = sb + SM_TBASE + (c & (NSTG - 1)) * SM_BUF;
        #pragma unroll
        for (int s = 0; s < 4; ++s) {
            uint32_t ah_[2][4], al_[2][4], wh_[2][4], wl_[2][4];
            const uint32_t akx = (uint32_t)((32 * s + a_kb) ^ mask);
            const uint32_t bkx = (uint32_t)((32 * s + b_kb) ^ mask);
            #pragma unroll
            for (int mi = 0; mi < 2; ++mi) {
                ldsm4(ah_[mi], tb + OFF_AH + arow128[mi] + akx);
                ldsm4(al_[mi], tb + OFF_AL + arow128[mi] + akx);
            }
            #pragma unroll
            for (int nj = 0; nj < 2; ++nj) {
                ldsm4(wh_[nj], tb + OFF_WH + brow128[nj] + bkx);
                ldsm4(wl_[nj], tb + OFF_WL + brow128[nj] + bkx);
            }
            // term-major: 8 independent accumulators between reuses
            #pragma unroll
            for (int mi = 0; mi < 2; ++mi)
                #pragma unroll
                for (int nj = 0; nj < 2; ++nj)
                    #pragma unroll
                    for (int h = 0; h < 2; ++h)
                        mma16816(d[mi][nj * 2 + h], ah_[mi], &wh_[nj][h * 2]);
            #pragma unroll
            for (int mi = 0; mi < 2; ++mi)
                #pragma unroll
                for (int nj = 0; nj < 2; ++nj)
                    #pragma unroll
                    for (int h = 0; h < 2; ++h)
                        mma16816(d[mi][nj * 2 + h], ah_[mi], &wl_[nj][h * 2]);
            #pragma unroll
            for (int mi = 0; mi < 2; ++mi)
                #pragma unroll
                for (int nj = 0; nj < 2; ++nj)
                    #pragma unroll
                    for (int h = 0; h < 2; ++h)
                        mma16816(d[mi][nj * 2 + h], al_[mi], &wh_[nj][h * 2]);
        }
    }
}

// store warp accumulators into padded fp32 gates tile gs[128][GS_STRIDE]
__device__ __forceinline__ void store_gates(float* gs, const float d[2][4][4], int tid) {
    const int wid = tid >> 5, lane = tid & 31;
    const int wm = wid & 3, wn = wid >> 2;
    const int trow = wm * 32 + (lane >> 2);
    const int tcol = wn * 32 + (lane & 3) * 2;
    #pragma unroll
    for (int mi = 0; mi < 2; ++mi)
        #pragma unroll
        for (int ni = 0; ni < 4; ++ni) {
            const int r0 = trow + mi * 16, cc = tcol + ni * 8;
            *(float2*)(gs + r0 * GS_STRIDE + cc)       = make_float2(d[mi][ni][0], d[mi][ni][1]);
            *(float2*)(gs + (r0 + 8) * GS_STRIDE + cc) = make_float2(d[mi][ni][2], d[mi][ni][3]);
        }
}

// ================= prep kernels =================
__global__ void prep_w(const float* __restrict__ Wih, const float* __restrict__ Whh) {
    for (int idx = blockIdx.x * blockDim.x + threadIdx.x; idx < LL * GG * KTOT; idx += gridDim.x * blockDim.x) {
        int k = idx & 1023, n = (idx >> 10) & 2047, l = idx >> 21;
        int unit = ((n >> 6) << 4) | ((n >> 2) & 15);   // gate-interleaved permute
        int gate = n & 3;
        int src = gate * HH + unit;
        float v = (k < HH) ? Wih[((size_t)l * GG + src) * HH + k]
                           : Whh[((size_t)l * GG + src) * HH + (k - HH)];
        __nv_bfloat16 hi = __float2bfloat16(v);
        g_w_hi[idx] = hi;
        g_w_lo[idx] = __float2bfloat16(v - __bfloat162float(hi));
    }
}
__global__ void prep_wo(const float* __restrict__ Wout) {
    for (size_t idx = blockIdx.x * blockDim.x + threadIdx.x; idx < (size_t)VV * HH; idx += (size_t)gridDim.x * blockDim.x) {
        float v = Wout[idx];
        __nv_bfloat16 hi = __float2bfloat16(v);
        g_wo_hi[idx] = hi;
        g_wo_lo[idx] = __float2bfloat16(v - __bfloat162float(hi));
    }
}
__global__ void prep_e(const int* __restrict__ x, const float* __restrict__ emb) {
    for (int idx = blockIdx.x * blockDim.x + threadIdx.x; idx < SSTEPS * BB * HH; idx += gridDim.x * blockDim.x) {
        int k = idx & 511, b = (idx >> 9) & 255, t = idx >> 17;
        int tok = x[t * BB + b];   // torch .view(S,B,-1) reinterpretation
        float v = emb[(size_t)tok * HH + k];
        __nv_bfloat16 hi = __float2bfloat16(v);
        g_e_hi[idx] = hi;
        g_e_lo[idx] = __float2bfloat16(v - __bfloat162float(hi));
    }
}

// ================= main persistent kernel =================
__global__ void __launch_bounds__(NTHR, 1)
lstm_mma(const float* __restrict__ h0, const float* __restrict__ c0,
         const float* __restrict__ bih, const float* __restrict__ bhh,
         const float* __restrict__ bout, float* __restrict__ out)
{
    extern __shared__ __align__(1024) char smem[];
    const uint32_t sb = smem_u32(smem);
    const int tid = threadIdx.x, bid = blockIdx.x;
    const int kh = bid & 1;           // K half
    const int nb = (bid >> 1) & 31;   // N tile (64 gate cols = 16 units)
    const int mq = bid >> 6;          // batch half (128 rows)

    float* bias_s = (float*)(smem + SM_BIAS);
    float* gs     = (float*)(smem + SM_TBASE);   // phase-2 only (stage-0 buffer dead then)

    for (int j = tid; j < LL * 64; j += NTHR) {
        int l = j >> 6, nl = j & 63;
        int gi = l * GG + (nl & 3) * HH + nb * 16 + (nl >> 2);
        bias_s[j] = bih[gi] + bhh[gi];
    }
    // c slice init: this CTA owns rows [mq*128 + kh*64, +64), units [nb*16, +16)
    for (int j = tid; j < LL * 64 * 16; j += NTHR) {
        int l = j >> 10, r = (j >> 4) & 63, u = j & 15;
        size_t idx = ((size_t)l * BB + mq * 128 + kh * 64 + r) * HH + nb * 16 + u;
        g_c[idx] = c0[idx];
    }
    // h0 split (cooperative)
    for (int i = bid * NTHR + tid; i < LL * BB * HH; i += NCTA * NTHR) {
        float v = h0[i];
        __nv_bfloat16 hi = __float2bfloat16(v);
        g_h_hi[LL * BB * HH + i] = hi;
        g_h_lo[LL * BB * HH + i] = __float2bfloat16(v - __bfloat162float(hi));
    }
    if (kh == 0 && tid == 0) atomicExch(&g_pairflag[mq * 32 + nb], 0u);  // replay-safe reset
    grid_sync();

    const size_t row0 = (size_t)(mq * 128) * HH;
    float d[2][4][4];
    float* mypart       = g_part + ((size_t)((kh * 2 + mq) * 32 + nb) * NTHR + tid) * (LL * 32);
    const float* thpart = g_part + ((size_t)(((kh ^ 1) * 2 + mq) * 32 + nb) * NTHR + tid) * (LL * 32);
    unsigned* pflag = &g_pairflag[mq * 32 + nb];
    unsigned pair_exp = 0;

    // ======== wavefront: diagonal dg = t + l; cells on a diagonal are independent ========
    #pragma unroll 1
    for (int dg = 0; dg < SSTEPS + LL - 1; ++dg) {
        const int l_lo = (dg > SSTEPS - 1) ? (dg - (SSTEPS - 1)) : 0;
        const int l_hi = (dg < LL - 1) ? dg : (LL - 1);

        // ---- phase 1: GEMMs for all cells, partials -> gmem ----
        #pragma unroll 1
        for (int l = l_lo; l <= l_hi; ++l) {
            const int t = dg - l;
            const int cur = t & 1, prev = cur ^ 1;
            const __nv_bfloat16 *ah0, *al0;
            if (kh == 0) {
                if (l == 0) {
                    ah0 = g_e_hi + (size_t)t * BB * HH + row0;
                    al0 = g_e_lo + (size_t)t * BB * HH + row0;
                } else {
                    size_t o = ((size_t)cur * LL + (l - 1)) * BB * HH + row0;
                    ah0 = g_h_hi + o; al0 = g_h_lo + o;
                }
            } else {
                size_t o = ((size_t)prev * LL + l) * BB * HH + row0;
                ah0 = g_h_hi + o; al0 = g_h_lo + o;
            }
            const __nv_bfloat16* wbh = g_w_hi + ((size_t)l * GG + nb * 64) * KTOT + kh * (NCHL * KC);
            const __nv_bfloat16* wbl = g_w_lo + ((size_t)l * GG + nb * 64) * KTOT + kh * (NCHL * KC);

            gemm_mma(d, sb, tid, NCHL, ah0, al0, wbh, wbl, KTOT);

            float* mp = mypart + (l - l_lo) * 32;
            #pragma unroll
            for (int mi = 0; mi < 2; ++mi)
                #pragma unroll
                for (int ni = 0; ni < 4; ++ni)
                    *(float4*)(mp + (mi * 4 + ni) * 4) = *(const float4*)d[mi][ni];
        }

        // ---- exchange: one flag per diagonal ----
        __threadfence();
        __syncthreads();
        if (tid == 0) atomicAdd(pflag, 1u);
        pair_exp += 2;
        if (tid == 0) {
            while (*((volatile unsigned*)pflag) < pair_exp) { __nanosleep(20); }
        }
        __syncthreads();

        // ---- phase 2: combine + activation per cell ----
        #pragma unroll 1
        for (int l = l_lo; l <= l_hi; ++l) {
            const int t = dg - l;
            const int cur = t & 1;
            const int ci = (l - l_lo) * 32;
            #pragma unroll
            for (int mi = 0; mi < 2; ++mi)
                #pragma unroll
                for (int ni = 0; ni < 4; ++ni) {
                    const float4 m4 = *(const float4*)(mypart + ci + (mi * 4 + ni) * 4);
                    const float4 p4 = ldcg4(thpart + ci + (mi * 4 + ni) * 4);
                    d[mi][ni][0] = m4.x + p4.x; d[mi][ni][1] = m4.y + p4.y;
                    d[mi][ni][2] = m4.z + p4.z; d[mi][ni][3] = m4.w + p4.w;
                }
            store_gates(gs, d, tid);
            __syncthreads();
            // activation: this CTA's 64-row half (1024 items, 4/thread)
            #pragma unroll
            for (int i = 0; i < 4; ++i) {
                const int j = tid + NTHR * i;
                const int r = j >> 4, u = j & 15;
                const int row = kh * 64 + r;
                const float* gr = gs + row * GS_STRIDE + 4 * u;
                const int b = mq * 128 + row;
                const float gi = gr[0] + bias_s[l * 64 + 4 * u + 0];
                const float gf = gr[1] + bias_s[l * 64 + 4 * u + 1];
                const float gg = gr[2] + bias_s[l * 64 + 4 * u + 2];
                const float go = gr[3] + bias_s[l * 64 + 4 * u + 3];
                const size_t cidx = ((size_t)l * BB + b) * HH + nb * 16 + u;
                const float cn = sigf(gf) * g_c[cidx] + sigf(gi) * tanhft(gg);
                g_c[cidx] = cn;
                const float hv = sigf(go) * tanhft(cn);
                const size_t ho = ((size_t)cur * LL + l) * BB * HH + (size_t)b * HH + nb * 16 + u;
                __nv_bfloat16 hi = __float2bfloat16(hv);
                g_h_hi[ho] = hi;
                g_h_lo[ho] = __float2bfloat16(hv - __bfloat162float(hi));
            }
            __syncthreads();   // gs free before next cell reuses it
        }
        grid_sync();   // diagonal complete: h of all cells visible chip-wide
    }

    // ---- output GEMM: logits 256x32000, K=512 -> 2 x 500 = 1000 tiles of 128x64 ----
    const size_t hf = ((size_t)((SSTEPS - 1) & 1) * LL + (LL - 1)) * BB * HH;
    #pragma unroll 1
    for (int tt = bid; tt < 1000; tt += NCTA) {
        const int b0 = (tt / 500) * 128;
        const int v0 = (tt % 500) * 64;
        gemm_mma(d, sb, tid, NCHO,
                 g_h_hi + hf + (size_t)b0 * HH, g_h_lo + hf + (size_t)b0 * HH,
                 g_wo_hi + (size_t)v0 * HH, g_wo_lo + (size_t)v0 * HH, HH);
        store_gates(gs, d, tid);
        __syncthreads();
        if (tid < 128) {
            const float* gr = gs + tid * GS_STRIDE;
            float* op = out + (size_t)(b0 + tid) * VV + v0;
            #pragma unroll
            for (int c4 = 0; c4 < 16; ++c4) {
                float4 s;
                s.x = gr[4*c4+0] + bout[v0 + 4*c4+0];
                s.y = gr[4*c4+1] + bout[v0 + 4*c4+1];
                s.z = gr[4*c4+2] + bout[v0 + 4*c4+2];
                s.w = gr[4*c4+3] + bout[v0 + 4*c4+3];
                *(float4*)(op + 4*c4) = s;
            }
        }
        __syncthreads();   // gs free before next tile's cp.async overwrites it
    }
}

extern "C" void kernel_launch(void* const* d_in, const int* in_sizes, int n_in,
                              void* d_out, int out_size) {
    (void)in_sizes; (void)n_in; (void)out_size;
    prep_w<<<2048, 256>>>((const float*)d_in[4], (const float*)d_in[5]);
    prep_wo<<<2048, 256>>>((const float*)d_in[8]);
    prep_e<<<2048, 256>>>((const int*)d_in[0], (const float*)d_in[3]);
    cudaFuncSetAttribute(lstm_mma, cudaFuncAttributeMaxDynamicSharedMemorySize, SMEM_TOTAL);
    lstm_mma<<<NCTA, NTHR, SMEM_TOTAL>>>(
        (const float*)d_in[1],   // h0
        (const float*)d_in[2],   // c0
        (const float*)d_in[6],   // b_ih
        (const float*)d_in[7],   // b_hh
        (const float*)d_in[9],   // b_out
        (float*)d_out);
}

// round 12
// speedup vs baseline: 4.6612x; 1.0240x over previous
#include <cuda_runtime.h>
#include <cuda_bf16.h>
#include <math.h>
#include <stdint.h>

#define LL 5
#define BB 256
#define HH 512
#define GG 2048
#define SSTEPS 128
#define VV 32000
#define KTOT 1024

#define NCTA 128
#define NTHR 512
#define KC 64          // k elems per chunk (64 bf16 = 128B row = SW128 atom)
#define NCHL 8         // chunks per half-K layer GEMM (K=512 per CTA)
#define NCHO 8         // chunks per output GEMM (K=512)
#define NSTG 4         // cp.async pipeline stages

// dynamic SMEM layout (bytes)
#define SM_BIAS  128   // 5*64 floats
#define SM_TBASE 2048
#define SM_BUF   49152 // A_hi 16K | A_lo 16K | W_hi 8K | W_lo 8K
#define OFF_AH 0
#define OFF_AL 16384
#define OFF_WH 32768
#define OFF_WL 40960
#define SMEM_TOTAL (SM_TBASE + NSTG*SM_BUF)   // 198656
#define GS_STRIDE 66   // fp32 gates tile row stride (gs overlays stage-0 buffer, phase-2 only)

// ---- persistent device scratch ----
__device__ __align__(16) __nv_bfloat16 g_w_hi[LL*GG*KTOT];
__device__ __align__(16) __nv_bfloat16 g_w_lo[LL*GG*KTOT];
__device__ __align__(16) __nv_bfloat16 g_wo_hi[(size_t)VV*HH];
__device__ __align__(16) __nv_bfloat16 g_wo_lo[(size_t)VV*HH];
__device__ __align__(16) __nv_bfloat16 g_e_hi[(size_t)SSTEPS*BB*HH];
__device__ __align__(16) __nv_bfloat16 g_e_lo[(size_t)SSTEPS*BB*HH];
__device__ __align__(16) __nv_bfloat16 g_h_hi[2*LL*BB*HH];
__device__ __align__(16) __nv_bfloat16 g_h_lo[2*LL*BB*HH];
__device__ float    g_c[(size_t)LL*BB*HH];
__device__ __align__(16) float g_part[(size_t)2*2*32*NTHR*LL*16];  // [kh][mq][nb][tid][cell][16]
__device__ unsigned g_pairflag[2*32];                              // [mq][nb]
__device__ unsigned g_bar_count;
__device__ unsigned g_bar_gen;

// ================= helpers =================
#define SWZ128(o) ((o) ^ (((o) >> 3) & 0x70))

__device__ __forceinline__ uint32_t smem_u32(const void* p) {
    uint32_t a;
    asm("{ .reg .u64 t; cvta.to.shared.u64 t, %1; cvt.u32.u64 %0, t; }" : "=r"(a) : "l"(p));
    return a;
}
__device__ __forceinline__ void cp16(uint32_t d, const void* s) {
    asm volatile("cp.async.cg.shared.global [%0], [%1], 16;" :: "r"(d), "l"(s));
}
__device__ __forceinline__ void cp_commit() { asm volatile("cp.async.commit_group;" ::: "memory"); }
__device__ __forceinline__ void cp_wait2()  { asm volatile("cp.async.wait_group 2;" ::: "memory"); }
__device__ __forceinline__ void cp_wait1()  { asm volatile("cp.async.wait_group 1;" ::: "memory"); }
__device__ __forceinline__ void cp_wait0()  { asm volatile("cp.async.wait_group 0;" ::: "memory"); }

__device__ __forceinline__ void ldsm4(uint32_t* r, uint32_t a) {
    asm volatile("ldmatrix.sync.aligned.m8n8.x4.shared.b16 {%0,%1,%2,%3}, [%4];"
        : "=r"(r[0]), "=r"(r[1]), "=r"(r[2]), "=r"(r[3]) : "r"(a));
}
__device__ __forceinline__ void mma16816(float* d, const uint32_t* a, const uint32_t* b) {
    asm volatile("mma.sync.aligned.m16n8k16.row.col.f32.bf16.bf16.f32 "
        "{%0,%1,%2,%3}, {%4,%5,%6,%7}, {%8,%9}, {%0,%1,%2,%3};"
        : "+f"(d[0]), "+f"(d[1]), "+f"(d[2]), "+f"(d[3])
        : "r"(a[0]), "r"(a[1]), "r"(a[2]), "r"(a[3]), "r"(b[0]), "r"(b[1]));
}
// L2-coherent float4 load (bypasses L1 -> always sees partner CTA's STGs)
__device__ __forceinline__ float4 ldcg4(const float* p) {
    float4 v;
    asm volatile("ld.global.cg.v4.f32 {%0,%1,%2,%3}, [%4];"
        : "=f"(v.x), "=f"(v.y), "=f"(v.z), "=f"(v.w) : "l"(p));
    return v;
}

__device__ __forceinline__ float sigf(float v)   { return 1.0f / (1.0f + __expf(-v)); }
__device__ __forceinline__ float tanhft(float v) { return 2.0f / (1.0f + __expf(-2.0f * v)) - 1.0f; }

__device__ __forceinline__ void grid_sync() {
    __syncthreads();
    if (threadIdx.x == 0) {
        __threadfence();
        unsigned gen = *((volatile unsigned*)&g_bar_gen);
        if (atomicAdd(&g_bar_count, 1u) == NCTA - 1u) {
            atomicExch(&g_bar_count, 0u);
            __threadfence();
            atomicAdd(&g_bar_gen, 1u);
        } else {
            while (*((volatile unsigned*)&g_bar_gen) == gen) { __nanosleep(32); }
        }
        __threadfence();
    }
    __syncthreads();
}

// cp.async one chunk (512 threads): A 128x64 bf16 (hi,lo) + W 64x64 bf16 (hi,lo)
__device__ __forceinline__ void issue_chunk(uint32_t tb,
    const __nv_bfloat16* ah, const __nv_bfloat16* al,
    const __nv_bfloat16* wh, const __nv_bfloat16* wl, int wstride, int tid)
{
    #pragma unroll
    for (int j = 0; j < 2; ++j) {
        int g = tid + NTHR * j, m = g >> 3, q = g & 7;
        uint32_t so = SWZ128((uint32_t)(m * 128 + q * 16));
        cp16(tb + OFF_AH + so, ah + (size_t)m * HH + q * 8);
        cp16(tb + OFF_AL + so, al + (size_t)m * HH + q * 8);
    }
    {
        int m = tid >> 3, q = tid & 7;
        uint32_t so = SWZ128((uint32_t)(m * 128 + q * 16));
        cp16(tb + OFF_WH + so, wh + (size_t)m * wstride + q * 8);
        cp16(tb + OFF_WL + so, wl + (size_t)m * wstride + q * 8);
    }
    cp_commit();
}

// 4-stage pipelined split-bf16 HMMA GEMM. D(128x64) in regs.
// 16 warps = 4m x 4n; warp tile 32x16 -> d[2 mfrag][2 nfrag][4].
__device__ void gemm_mma(float d[2][2][4], uint32_t sb, int tid, int nch,
    const __nv_bfloat16* ah0, const __nv_bfloat16* al0,
    const __nv_bfloat16* wh,  const __nv_bfloat16* wl, int wstride)
{
    const int wid = tid >> 5, lane = tid & 31;
    const int wm = wid & 3, wn = wid >> 2;
    const int mask = (lane & 7) << 4;
    const int a_row = ((lane >> 3) & 1) * 8 + (lane & 7);
    const int a_kb  = ((lane >> 4) & 1) * 16;
    const int b_row = ((lane >> 4) & 1) * 8 + (lane & 7);
    const int b_kb  = ((lane >> 3) & 1) * 16;
    uint32_t arow128[2];
    #pragma unroll
    for (int i = 0; i < 2; ++i)
        arow128[i] = (uint32_t)((wm * 32 + i * 16 + a_row) * 128);
    const uint32_t brow128 = (uint32_t)((wn * 16 + b_row) * 128);

    #pragma unroll
    for (int mi = 0; mi < 2; ++mi)
        #pragma unroll
        for (int ni = 0; ni < 2; ++ni)
            #pragma unroll
            for (int r = 0; r < 4; ++r) d[mi][ni][r] = 0.0f;

    // prologue: prefetch chunks 0..NSTG-2
    #pragma unroll
    for (int p = 0; p < NSTG - 1; ++p)
        if (p < nch)
            issue_chunk(sb + SM_TBASE + p * SM_BUF, ah0 + p * KC, al0 + p * KC,
                        wh + p * KC, wl + p * KC, wstride, tid);

    #pragma unroll 1
    for (int c = 0; c < nch; ++c) {
        const int rem = nch - 1 - c;
        if (rem >= 2) cp_wait2(); else if (rem == 1) cp_wait1(); else cp_wait0();
        __syncthreads();
        if (c + NSTG - 1 < nch) {
            const int c2 = c + NSTG - 1;
            issue_chunk(sb + SM_TBASE + (c2 & (NSTG - 1)) * SM_BUF,
                        ah0 + c2 * KC, al0 + c2 * KC,
                        wh + c2 * KC, wl + c2 * KC, wstride, tid);
        }
        const uint32_t tb = sb + SM_TBASE + (c & (NSTG - 1)) * SM_BUF;
        #pragma unroll
        for (int s = 0; s < 4; ++s) {
            uint32_t ah_[2][4], al_[2][4], wh_[4], wl_[4];
            const uint32_t akx = (uint32_t)((32 * s + a_kb) ^ mask);
            const uint32_t bkx = (uint32_t)((32 * s + b_kb) ^ mask);
            #pragma unroll
            for (int mi = 0; mi < 2; ++mi) {
                ldsm4(ah_[mi], tb + OFF_AH + arow128[mi] + akx);
                ldsm4(al_[mi], tb + OFF_AL + arow128[mi] + akx);
            }
            ldsm4(wh_, tb + OFF_WH + brow128 + bkx);
            ldsm4(wl_, tb + OFF_WL + brow128 + bkx);
            // term-major: 4 independent accumulators between reuses
            #pragma unroll
            for (int mi = 0; mi < 2; ++mi)
                #pragma unroll
                for (int h = 0; h < 2; ++h)
                    mma16816(d[mi][h], ah_[mi], &wh_[h * 2]);
            #pragma unroll
            for (int mi = 0; mi < 2; ++mi)
                #pragma unroll
                for (int h = 0; h < 2; ++h)
                    mma16816(d[mi][h], ah_[mi], &wl_[h * 2]);
            #pragma unroll
            for (int mi = 0; mi < 2; ++mi)
                #pragma unroll
                for (int h = 0; h < 2; ++h)
                    mma16816(d[mi][h], al_[mi], &wh_[h * 2]);
        }
    }
}

// store warp accumulators into padded fp32 gates tile gs[128][GS_STRIDE]
__device__ __forceinline__ void store_gates(float* gs, const float d[2][2][4], int tid) {
    const int wid = tid >> 5, lane = tid & 31;
    const int wm = wid & 3, wn = wid >> 2;
    const int trow = wm * 32 + (lane >> 2);
    const int tcol = wn * 16 + (lane & 3) * 2;
    #pragma unroll
    for (int mi = 0; mi < 2; ++mi)
        #pragma unroll
        for (int ni = 0; ni < 2; ++ni) {
            const int r0 = trow + mi * 16, cc = tcol + ni * 8;
            *(float2*)(gs + r0 * GS_STRIDE + cc)       = make_float2(d[mi][ni][0], d[mi][ni][1]);
            *(float2*)(gs + (r0 + 8) * GS_STRIDE + cc) = make_float2(d[mi][ni][2], d[mi][ni][3]);
        }
}

// ================= prep kernels =================
__global__ void prep_w(const float* __restrict__ Wih, const float* __restrict__ Whh) {
    for (int idx = blockIdx.x * blockDim.x + threadIdx.x; idx < LL * GG * KTOT; idx += gridDim.x * blockDim.x) {
        int k = idx & 1023, n = (idx >> 10) & 2047, l = idx >> 21;
        int unit = ((n >> 6) << 4) | ((n >> 2) & 15);   // gate-interleaved permute
        int gate = n & 3;
        int src = gate * HH + unit;
        float v = (k < HH) ? Wih[((size_t)l * GG + src) * HH + k]
                           : Whh[((size_t)l * GG + src) * HH + (k - HH)];
        __nv_bfloat16 hi = __float2bfloat16(v);
        g_w_hi[idx] = hi;
        g_w_lo[idx] = __float2bfloat16(v - __bfloat162float(hi));
    }
}
__global__ void prep_wo(const float* __restrict__ Wout) {
    for (size_t idx = blockIdx.x * blockDim.x + threadIdx.x; idx < (size_t)VV * HH; idx += (size_t)gridDim.x * blockDim.x) {
        float v = Wout[idx];
        __nv_bfloat16 hi = __float2bfloat16(v);
        g_wo_hi[idx] = hi;
        g_wo_lo[idx] = __float2bfloat16(v - __bfloat162float(hi));
    }
}
__global__ void prep_e(const int* __restrict__ x, const float* __restrict__ emb) {
    for (int idx = blockIdx.x * blockDim.x + threadIdx.x; idx < SSTEPS * BB * HH; idx += gridDim.x * blockDim.x) {
        int k = idx & 511, b = (idx >> 9) & 255, t = idx >> 17;
        int tok = x[t * BB + b];   // torch .view(S,B,-1) reinterpretation
        float v = emb[(size_t)tok * HH + k];
        __nv_bfloat16 hi = __float2bfloat16(v);
        g_e_hi[idx] = hi;
        g_e_lo[idx] = __float2bfloat16(v - __bfloat162float(hi));
    }
}

// ================= main persistent kernel =================
__global__ void __launch_bounds__(NTHR, 1)
lstm_mma(const float* __restrict__ h0, const float* __restrict__ c0,
         const float* __restrict__ bih, const float* __restrict__ bhh,
         const float* __restrict__ bout, float* __restrict__ out)
{
    extern __shared__ __align__(1024) char smem[];
    const uint32_t sb = smem_u32(smem);
    const int tid = threadIdx.x, bid = blockIdx.x;
    const int kh = bid & 1;           // K half
    const int nb = (bid >> 1) & 31;   // N tile (64 gate cols = 16 units)
    const int mq = bid >> 6;          // batch half (128 rows)

    float* bias_s = (float*)(smem + SM_BIAS);
    float* gs     = (float*)(smem + SM_TBASE);   // phase-2 only (stage-0 buffer dead then)

    for (int j = tid; j < LL * 64; j += NTHR) {
        int l = j >> 6, nl = j & 63;
        int gi = l * GG + (nl & 3) * HH + nb * 16 + (nl >> 2);
        bias_s[j] = bih[gi] + bhh[gi];
    }
    // c slice init: this CTA owns rows [mq*128 + kh*64, +64), units [nb*16, +16)
    for (int j = tid; j < LL * 64 * 16; j += NTHR) {
        int l = j >> 10, r = (j >> 4) & 63, u = j & 15;
        size_t idx = ((size_t)l * BB + mq * 128 + kh * 64 + r) * HH + nb * 16 + u;
        g_c[idx] = c0[idx];
    }
    // h0 split (cooperative)
    for (int i = bid * NTHR + tid; i < LL * BB * HH; i += NCTA * NTHR) {
        float v = h0[i];
        __nv_bfloat16 hi = __float2bfloat16(v);
        g_h_hi[LL * BB * HH + i] = hi;
        g_h_lo[LL * BB * HH + i] = __float2bfloat16(v - __bfloat162float(hi));
    }
    if (kh == 0 && tid == 0) atomicExch(&g_pairflag[mq * 32 + nb], 0u);  // replay-safe reset
    grid_sync();

    const size_t row0 = (size_t)(mq * 128) * HH;
    float d[2][2][4];
    float* mypart       = g_part + ((size_t)((kh * 2 + mq) * 32 + nb) * NTHR + tid) * (LL * 16);
    const float* thpart = g_part + ((size_t)(((kh ^ 1) * 2 + mq) * 32 + nb) * NTHR + tid) * (LL * 16);
    unsigned* pflag = &g_pairflag[mq * 32 + nb];
    unsigned pair_exp = 0;

    // ======== wavefront: diagonal dg = t + l; cells on a diagonal are independent ========
    #pragma unroll 1
    for (int dg = 0; dg < SSTEPS + LL - 1; ++dg) {
        const int l_lo = (dg > SSTEPS - 1) ? (dg - (SSTEPS - 1)) : 0;
        const int l_hi = (dg < LL - 1) ? dg : (LL - 1);

        // ---- phase 1: GEMMs for all cells, partials -> gmem ----
        #pragma unroll 1
        for (int l = l_lo; l <= l_hi; ++l) {
            const int t = dg - l;
            const int cur = t & 1, prev = cur ^ 1;
            const __nv_bfloat16 *ah0, *al0;
            if (kh == 0) {
                if (l == 0) {
                    ah0 = g_e_hi + (size_t)t * BB * HH + row0;
                    al0 = g_e_lo + (size_t)t * BB * HH + row0;
                } else {
                    size_t o = ((size_t)cur * LL + (l - 1)) * BB * HH + row0;
                    ah0 = g_h_hi + o; al0 = g_h_lo + o;
                }
            } else {
                size_t o = ((size_t)prev * LL + l) * BB * HH + row0;
                ah0 = g_h_hi + o; al0 = g_h_lo + o;
            }
            const __nv_bfloat16* wbh = g_w_hi + ((size_t)l * GG + nb * 64) * KTOT + kh * (NCHL * KC);
            const __nv_bfloat16* wbl = g_w_lo + ((size_t)l * GG + nb * 64) * KTOT + kh * (NCHL * KC);

            gemm_mma(d, sb, tid, NCHL, ah0, al0, wbh, wbl, KTOT);

            float* mp = mypart + (l - l_lo) * 16;
            #pragma unroll
            for (int mi = 0; mi < 2; ++mi)
                #pragma unroll
                for (int ni = 0; ni < 2; ++ni)
                    *(float4*)(mp + (mi * 2 + ni) * 4) = *(const float4*)d[mi][ni];
        }

        // ---- exchange: one flag per diagonal ----
        __threadfence();
        __syncthreads();
        if (tid == 0) atomicAdd(pflag, 1u);
        pair_exp += 2;
        if (tid == 0) {
            while (*((volatile unsigned*)pflag) < pair_exp) { __nanosleep(20); }
        }
        __syncthreads();

        // ---- phase 2: combine + activation per cell ----
        #pragma unroll 1
        for (int l = l_lo; l <= l_hi; ++l) {
            const int t = dg - l;
            const int cur = t & 1;
            const int ci = (l - l_lo) * 16;
            #pragma unroll
            for (int mi = 0; mi < 2; ++mi)
                #pragma unroll
                for (int ni = 0; ni < 2; ++ni) {
                    const float4 m4 = *(const float4*)(mypart + ci + (mi * 2 + ni) * 4);
                    const float4 p4 = ldcg4(thpart + ci + (mi * 2 + ni) * 4);
                    d[mi][ni][0] = m4.x + p4.x; d[mi][ni][1] = m4.y + p4.y;
                    d[mi][ni][2] = m4.z + p4.z; d[mi][ni][3] = m4.w + p4.w;
                }
            store_gates(gs, d, tid);
            __syncthreads();
            // activation: this CTA's 64-row half (1024 items, 2/thread)
            #pragma unroll
            for (int i = 0; i < 2; ++i) {
                const int j = tid + NTHR * i;
                const int r = j >> 4, u = j & 15;
                const int row = kh * 64 + r;
                const float* gr = gs + row * GS_STRIDE + 4 * u;
                const int b = mq * 128 + row;
                const float gi = gr[0] + bias_s[l * 64 + 4 * u + 0];
                const float gf = gr[1] + bias_s[l * 64 + 4 * u + 1];
                const float gg = gr[2] + bias_s[l * 64 + 4 * u + 2];
                const float go = gr[3] + bias_s[l * 64 + 4 * u + 3];
                const size_t cidx = ((size_t)l * BB + b) * HH + nb * 16 + u;
                const float cn = sigf(gf) * g_c[cidx] + sigf(gi) * tanhft(gg);
                g_c[cidx] = cn;
                const float hv = sigf(go) * tanhft(cn);
                const size_t ho = ((size_t)cur * LL + l) * BB * HH + (size_t)b * HH + nb * 16 + u;
                __nv_bfloat16 hi = __float2bfloat16(hv);
                g_h_hi[ho] = hi;
                g_h_lo[ho] = __float2bfloat16(hv - __bfloat162float(hi));
            }
            __syncthreads();   // gs free before next cell reuses it
        }
        grid_sync();   // diagonal complete: h of all cells visible chip-wide
    }

    // ---- output GEMM: logits 256x32000, K=512 -> 2 x 500 = 1000 tiles of 128x64 ----
    const size_t hf = ((size_t)((SSTEPS - 1) & 1) * LL + (LL - 1)) * BB * HH;
    #pragma unroll 1
    for (int tt = bid; tt < 1000; tt += NCTA) {
        const int b0 = (tt / 500) * 128;
        const int v0 = (tt % 500) * 64;
        gemm_mma(d, sb, tid, NCHO,
                 g_h_hi + hf + (size_t)b0 * HH, g_h_lo + hf + (size_t)b0 * HH,
                 g_wo_hi + (size_t)v0 * HH, g_wo_lo + (size_t)v0 * HH, HH);
        store_gates(gs, d, tid);
        __syncthreads();
        if (tid < 128) {
            const float* gr = gs + tid * GS_STRIDE;
            float* op = out + (size_t)(b0 + tid) * VV + v0;
            #pragma unroll
            for (int c4 = 0; c4 < 16; ++c4) {
                float4 s;
                s.x = gr[4*c4+0] + bout[v0 + 4*c4+0];
                s.y = gr[4*c4+1] + bout[v0 + 4*c4+1];
                s.z = gr[4*c4+2] + bout[v0 + 4*c4+2];
                s.w = gr[4*c4+3] + bout[v0 + 4*c4+3];
                *(float4*)(op + 4*c4) = s;
            }
        }
        __syncthreads();   // gs free before next tile's cp.async overwrites it
    }
}

extern "C" void kernel_launch(void* const* d_in, const int* in_sizes, int n_in,
                              void* d_out, int out_size) {
    (void)in_sizes; (void)n_in; (void)out_size;
    prep_w<<<2048, 256>>>((const float*)d_in[4], (const float*)d_in[5]);
    prep_wo<<<2048, 256>>>((const float*)d_in[8]);
    prep_e<<<2048, 256>>>((const int*)d_in[0], (const float*)d_in[3]);
    cudaFuncSetAttribute(lstm_mma, cudaFuncAttributeMaxDynamicSharedMemorySize, SMEM_TOTAL);
    lstm_mma<<<NCTA, NTHR, SMEM_TOTAL>>>(
        (const float*)d_in[1],   // h0
        (const float*)d_in[2],   // c0
        (const float*)d_in[6],   // b_ih
        (const float*)d_in[7],   // b_hh
        (const float*)d_in[9],   // b_out
        (float*)d_out);
}

// round 13
// speedup vs baseline: 6.9724x; 1.4958x over previous
#include <cuda_runtime.h>
#include <cuda_fp16.h>
#include <math.h>
#include <stdint.h>

#define LL 5
#define BB 256
#define HH 512
#define GG 2048
#define SSTEPS 128
#define VV 32000
#define KTOT 1024

#define NCTA 128
#define NTHR 512
#define KC 64          // k elems per chunk (64 fp16 = 128B row = SW128 atom)
#define NCHL 8         // chunks per half-K layer GEMM (K=512 per CTA)
#define NCHO 8         // chunks per output GEMM (K=512)
#define NSTG 4         // cp.async pipeline stages

// dynamic SMEM layout (bytes)
#define SM_BIAS  128   // 5*64 floats
#define SM_TBASE 2048
#define SM_BUF   24576 // A 16K | W 8K
#define OFF_A 0
#define OFF_W 16384
#define SM_GS  (SM_TBASE + NSTG*SM_BUF)        // 100352
#define GS_STRIDE 66
#define SMEM_TOTAL (SM_GS + 128*GS_STRIDE*4)   // 134144

// ---- persistent device scratch (all fp16 single precision-term) ----
__device__ __align__(16) __half g_w[LL*GG*KTOT];
__device__ __align__(16) __half g_wo[(size_t)VV*HH];
__device__ __align__(16) __half g_e[(size_t)SSTEPS*BB*HH];
__device__ __align__(16) __half g_h[2*LL*BB*HH];
__device__ float    g_c[(size_t)LL*BB*HH];
__device__ __align__(16) float g_part[(size_t)2*2*32*NTHR*LL*16];  // [kh][mq][nb][tid][cell][16]
__device__ unsigned g_pairflag[2*32];                              // [mq][nb]
__device__ unsigned g_bar_count;
__device__ unsigned g_bar_gen;

// ================= helpers =================
#define SWZ128(o) ((o) ^ (((o) >> 3) & 0x70))

__device__ __forceinline__ uint32_t smem_u32(const void* p) {
    uint32_t a;
    asm("{ .reg .u64 t; cvta.to.shared.u64 t, %1; cvt.u32.u64 %0, t; }" : "=r"(a) : "l"(p));
    return a;
}
__device__ __forceinline__ void cp16(uint32_t d, const void* s) {
    asm volatile("cp.async.cg.shared.global [%0], [%1], 16;" :: "r"(d), "l"(s));
}
__device__ __forceinline__ void cp_commit() { asm volatile("cp.async.commit_group;" ::: "memory"); }
__device__ __forceinline__ void cp_wait2()  { asm volatile("cp.async.wait_group 2;" ::: "memory"); }
__device__ __forceinline__ void cp_wait1()  { asm volatile("cp.async.wait_group 1;" ::: "memory"); }
__device__ __forceinline__ void cp_wait0()  { asm volatile("cp.async.wait_group 0;" ::: "memory"); }

__device__ __forceinline__ void ldsm4(uint32_t* r, uint32_t a) {
    asm volatile("ldmatrix.sync.aligned.m8n8.x4.shared.b16 {%0,%1,%2,%3}, [%4];"
        : "=r"(r[0]), "=r"(r[1]), "=r"(r[2]), "=r"(r[3]) : "r"(a));
}
__device__ __forceinline__ void mma16816(float* d, const uint32_t* a, const uint32_t* b) {
    asm volatile("mma.sync.aligned.m16n8k16.row.col.f32.f16.f16.f32 "
        "{%0,%1,%2,%3}, {%4,%5,%6,%7}, {%8,%9}, {%0,%1,%2,%3};"
        : "+f"(d[0]), "+f"(d[1]), "+f"(d[2]), "+f"(d[3])
        : "r"(a[0]), "r"(a[1]), "r"(a[2]), "r"(a[3]), "r"(b[0]), "r"(b[1]));
}
// L2-coherent float4 load (bypasses L1 -> always sees partner CTA's STGs)
__device__ __forceinline__ float4 ldcg4(const float* p) {
    float4 v;
    asm volatile("ld.global.cg.v4.f32 {%0,%1,%2,%3}, [%4];"
        : "=f"(v.x), "=f"(v.y), "=f"(v.z), "=f"(v.w) : "l"(p));
    return v;
}

__device__ __forceinline__ float sigf(float v)   { return 1.0f / (1.0f + __expf(-v)); }
__device__ __forceinline__ float tanhft(float v) { return 2.0f / (1.0f + __expf(-2.0f * v)) - 1.0f; }

__device__ __forceinline__ void grid_sync() {
    __syncthreads();
    if (threadIdx.x == 0) {
        __threadfence();
        unsigned gen = *((volatile unsigned*)&g_bar_gen);
        if (atomicAdd(&g_bar_count, 1u) == NCTA - 1u) {
            atomicExch(&g_bar_count, 0u);
            __threadfence();
            atomicAdd(&g_bar_gen, 1u);
        } else {
            while (*((volatile unsigned*)&g_bar_gen) == gen) { __nanosleep(32); }
        }
        __threadfence();
    }
    __syncthreads();
}

// cp.async one chunk (512 threads): A 128x64 fp16 + W 64x64 fp16, SW128 swizzled
__device__ __forceinline__ void issue_chunk(uint32_t tb,
    const __half* a, const __half* w, int wstride, int tid)
{
    #pragma unroll
    for (int j = 0; j < 2; ++j) {
        int g = tid + NTHR * j, m = g >> 3, q = g & 7;
        uint32_t so = SWZ128((uint32_t)(m * 128 + q * 16));
        cp16(tb + OFF_A + so, a + (size_t)m * HH + q * 8);
    }
    {
        int m = tid >> 3, q = tid & 7;
        uint32_t so = SWZ128((uint32_t)(m * 128 + q * 16));
        cp16(tb + OFF_W + so, w + (size_t)m * wstride + q * 8);
    }
    cp_commit();
}

// 4-stage pipelined fp16 HMMA GEMM. D(128x64) in regs.
// 16 warps = 4m x 4n; warp tile 32x16 -> d[2 mfrag][2 nfrag][4].
__device__ void gemm_mma(float d[2][2][4], uint32_t sb, int tid, int nch,
    const __half* a0, const __half* w0, int wstride)
{
    const int wid = tid >> 5, lane = tid & 31;
    const int wm = wid & 3, wn = wid >> 2;
    const int mask = (lane & 7) << 4;
    const int a_row = ((lane >> 3) & 1) * 8 + (lane & 7);
    const int a_kb  = ((lane >> 4) & 1) * 16;
    const int b_row = ((lane >> 4) & 1) * 8 + (lane & 7);
    const int b_kb  = ((lane >> 3) & 1) * 16;
    uint32_t arow128[2];
    #pragma unroll
    for (int i = 0; i < 2; ++i)
        arow128[i] = (uint32_t)((wm * 32 + i * 16 + a_row) * 128);
    const uint32_t brow128 = (uint32_t)((wn * 16 + b_row) * 128);

    #pragma unroll
    for (int mi = 0; mi < 2; ++mi)
        #pragma unroll
        for (int ni = 0; ni < 2; ++ni)
            #pragma unroll
            for (int r = 0; r < 4; ++r) d[mi][ni][r] = 0.0f;

    // prologue: prefetch chunks 0..NSTG-2
    #pragma unroll
    for (int p = 0; p < NSTG - 1; ++p)
        if (p < nch)
            issue_chunk(sb + SM_TBASE + p * SM_BUF, a0 + p * KC, w0 + p * KC, wstride, tid);

    #pragma unroll 1
    for (int c = 0; c < nch; ++c) {
        const int rem = nch - 1 - c;
        if (rem >= 2) cp_wait2(); else if (rem == 1) cp_wait1(); else cp_wait0();
        __syncthreads();
        if (c + NSTG - 1 < nch) {
            const int c2 = c + NSTG - 1;
            issue_chunk(sb + SM_TBASE + (c2 & (NSTG - 1)) * SM_BUF,
                        a0 + c2 * KC, w0 + c2 * KC, wstride, tid);
        }
        const uint32_t tb = sb + SM_TBASE + (c & (NSTG - 1)) * SM_BUF;
        #pragma unroll
        for (int s = 0; s < 4; ++s) {
            uint32_t a_[2][4], w_[4];
            const uint32_t akx = (uint32_t)((32 * s + a_kb) ^ mask);
            const uint32_t bkx = (uint32_t)((32 * s + b_kb) ^ mask);
            #pragma unroll
            for (int mi = 0; mi < 2; ++mi)
                ldsm4(a_[mi], tb + OFF_A + arow128[mi] + akx);
            ldsm4(w_, tb + OFF_W + brow128 + bkx);
            #pragma unroll
            for (int mi = 0; mi < 2; ++mi)
                #pragma unroll
                for (int h = 0; h < 2; ++h)
                    mma16816(d[mi][h], a_[mi], &w_[h * 2]);
        }
    }
}

// store warp accumulators into padded fp32 gates tile gs[128][GS_STRIDE]
__device__ __forceinline__ void store_gates(float* gs, const float d[2][2][4], int tid) {
    const int wid = tid >> 5, lane = tid & 31;
    const int wm = wid & 3, wn = wid >> 2;
    const int trow = wm * 32 + (lane >> 2);
    const int tcol = wn * 16 + (lane & 3) * 2;
    #pragma unroll
    for (int mi = 0; mi < 2; ++mi)
        #pragma unroll
        for (int ni = 0; ni < 2; ++ni) {
            const int r0 = trow + mi * 16, cc = tcol + ni * 8;
            *(float2*)(gs + r0 * GS_STRIDE + cc)       = make_float2(d[mi][ni][0], d[mi][ni][1]);
            *(float2*)(gs + (r0 + 8) * GS_STRIDE + cc) = make_float2(d[mi][ni][2], d[mi][ni][3]);
        }
}

// ================= prep kernels =================
__global__ void prep_w(const float* __restrict__ Wih, const float* __restrict__ Whh) {
    for (int idx = blockIdx.x * blockDim.x + threadIdx.x; idx < LL * GG * KTOT; idx += gridDim.x * blockDim.x) {
        int k = idx & 1023, n = (idx >> 10) & 2047, l = idx >> 21;
        int unit = ((n >> 6) << 4) | ((n >> 2) & 15);   // gate-interleaved permute
        int gate = n & 3;
        int src = gate * HH + unit;
        float v = (k < HH) ? Wih[((size_t)l * GG + src) * HH + k]
                           : Whh[((size_t)l * GG + src) * HH + (k - HH)];
        g_w[idx] = __float2half(v);
    }
}
__global__ void prep_wo(const float* __restrict__ Wout) {
    for (size_t idx = blockIdx.x * blockDim.x + threadIdx.x; idx < (size_t)VV * HH; idx += (size_t)gridDim.x * blockDim.x)
        g_wo[idx] = __float2half(Wout[idx]);
}
__global__ void prep_e(const int* __restrict__ x, const float* __restrict__ emb) {
    for (int idx = blockIdx.x * blockDim.x + threadIdx.x; idx < SSTEPS * BB * HH; idx += gridDim.x * blockDim.x) {
        int k = idx & 511, b = (idx >> 9) & 255, t = idx >> 17;
        int tok = x[t * BB + b];   // torch .view(S,B,-1) reinterpretation
        g_e[idx] = __float2half(emb[(size_t)tok * HH + k]);
    }
}

// ================= main persistent kernel =================
__global__ void __launch_bounds__(NTHR, 1)
lstm_mma(const float* __restrict__ h0, const float* __restrict__ c0,
         const float* __restrict__ bih, const float* __restrict__ bhh,
         const float* __restrict__ bout, float* __restrict__ out)
{
    extern __shared__ __align__(1024) char smem[];
    const uint32_t sb = smem_u32(smem);
    const int tid = threadIdx.x, bid = blockIdx.x;
    const int kh = bid & 1;           // K half
    const int nb = (bid >> 1) & 31;   // N tile (64 gate cols = 16 units)
    const int mq = bid >> 6;          // batch half (128 rows)

    float* bias_s = (float*)(smem + SM_BIAS);
    float* gs     = (float*)(smem + SM_GS);

    for (int j = tid; j < LL * 64; j += NTHR) {
        int l = j >> 6, nl = j & 63;
        int gi = l * GG + (nl & 3) * HH + nb * 16 + (nl >> 2);
        bias_s[j] = bih[gi] + bhh[gi];
    }
    // c slice init: this CTA owns rows [mq*128 + kh*64, +64), units [nb*16, +16)
    for (int j = tid; j < LL * 64 * 16; j += NTHR) {
        int l = j >> 10, r = (j >> 4) & 63, u = j & 15;
        size_t idx = ((size_t)l * BB + mq * 128 + kh * 64 + r) * HH + nb * 16 + u;
        g_c[idx] = c0[idx];
    }
    // h0 -> fp16 (cooperative)
    for (int i = bid * NTHR + tid; i < LL * BB * HH; i += NCTA * NTHR)
        g_h[LL * BB * HH + i] = __float2half(h0[i]);
    if (kh == 0 && tid == 0) atomicExch(&g_pairflag[mq * 32 + nb], 0u);  // replay-safe reset
    grid_sync();

    const size_t row0 = (size_t)(mq * 128) * HH;
    float d[2][2][4];
    float* mypart       = g_part + ((size_t)((kh * 2 + mq) * 32 + nb) * NTHR + tid) * (LL * 16);
    const float* thpart = g_part + ((size_t)(((kh ^ 1) * 2 + mq) * 32 + nb) * NTHR + tid) * (LL * 16);
    unsigned* pflag = &g_pairflag[mq * 32 + nb];
    unsigned pair_exp = 0;

    // ======== wavefront: diagonal dg = t + l; cells on a diagonal are independent ========
    #pragma unroll 1
    for (int dg = 0; dg < SSTEPS + LL - 1; ++dg) {
        const int l_lo = (dg > SSTEPS - 1) ? (dg - (SSTEPS - 1)) : 0;
        const int l_hi = (dg < LL - 1) ? dg : (LL - 1);

        // ---- phase 1: GEMMs for all cells, partials -> gmem ----
        #pragma unroll 1
        for (int l = l_lo; l <= l_hi; ++l) {
            const int t = dg - l;
            const int cur = t & 1, prev = cur ^ 1;
            const __half* a0;
            if (kh == 0) {
                if (l == 0) a0 = g_e + (size_t)t * BB * HH + row0;
                else        a0 = g_h + ((size_t)cur * LL + (l - 1)) * BB * HH + row0;
            } else {
                a0 = g_h + ((size_t)prev * LL + l) * BB * HH + row0;
            }
            const __half* wb = g_w + ((size_t)l * GG + nb * 64) * KTOT + kh * (NCHL * KC);

            gemm_mma(d, sb, tid, NCHL, a0, wb, KTOT);

            float* mp = mypart + (l - l_lo) * 16;
            #pragma unroll
            for (int mi = 0; mi < 2; ++mi)
                #pragma unroll
                for (int ni = 0; ni < 2; ++ni)
                    *(float4*)(mp + (mi * 2 + ni) * 4) = *(const float4*)d[mi][ni];
        }

        // ---- exchange: one flag per diagonal ----
        __threadfence();
        __syncthreads();
        if (tid == 0) atomicAdd(pflag, 1u);
        pair_exp += 2;
        if (tid == 0) {
            while (*((volatile unsigned*)pflag) < pair_exp) { __nanosleep(20); }
        }
        __syncthreads();

        // ---- phase 2: combine + activation per cell ----
        #pragma unroll 1
        for (int l = l_lo; l <= l_hi; ++l) {
            const int t = dg - l;
            const int cur = t & 1;
            const int ci = (l - l_lo) * 16;
            #pragma unroll
            for (int mi = 0; mi < 2; ++mi)
                #pragma unroll
                for (int ni = 0; ni < 2; ++ni) {
                    const float4 m4 = *(const float4*)(mypart + ci + (mi * 2 + ni) * 4);
                    const float4 p4 = ldcg4(thpart + ci + (mi * 2 + ni) * 4);
                    d[mi][ni][0] = m4.x + p4.x; d[mi][ni][1] = m4.y + p4.y;
                    d[mi][ni][2] = m4.z + p4.z; d[mi][ni][3] = m4.w + p4.w;
                }
            store_gates(gs, d, tid);
            __syncthreads();
            // activation: this CTA's 64-row half (1024 items, 2/thread)
            #pragma unroll
            for (int i = 0; i < 2; ++i) {
                const int j = tid + NTHR * i;
                const int r = j >> 4, u = j & 15;
                const int row = kh * 64 + r;
                const float* gr = gs + row * GS_STRIDE + 4 * u;
                const int b = mq * 128 + row;
                const float gi = gr[0] + bias_s[l * 64 + 4 * u + 0];
                const float gf = gr[1] + bias_s[l * 64 + 4 * u + 1];
                const float gg = gr[2] + bias_s[l * 64 + 4 * u + 2];
                const float go = gr[3] + bias_s[l * 64 + 4 * u + 3];
                const size_t cidx = ((size_t)l * BB + b) * HH + nb * 16 + u;
                const float cn = sigf(gf) * g_c[cidx] + sigf(gi) * tanhft(gg);
                g_c[cidx] = cn;
                const float hv = sigf(go) * tanhft(cn);
                const size_t ho = ((size_t)cur * LL + l) * BB * HH + (size_t)b * HH + nb * 16 + u;
                g_h[ho] = __float2half(hv);
            }
            __syncthreads();   // gs free before next cell reuses it
        }
        grid_sync();   // diagonal complete: h of all cells visible chip-wide
    }

    // ---- output GEMM: logits 256x32000, K=512 -> 2 x 500 = 1000 tiles of 128x64 ----
    const size_t hf = ((size_t)((SSTEPS - 1) & 1) * LL + (LL - 1)) * BB * HH;
    #pragma unroll 1
    for (int tt = bid; tt < 1000; tt += NCTA) {
        const int b0 = (tt / 500) * 128;
        const int v0 = (tt % 500) * 64;
        gemm_mma(d, sb, tid, NCHO,
                 g_h + hf + (size_t)b0 * HH, g_wo + (size_t)v0 * HH, HH);
        store_gates(gs, d, tid);
        __syncthreads();
        if (tid < 128) {
            const float* gr = gs + tid * GS_STRIDE;
            float* op = out + (size_t)(b0 + tid) * VV + v0;
            #pragma unroll
            for (int c4 = 0; c4 < 16; ++c4) {
                float4 s;
                s.x = gr[4*c4+0] + bout[v0 + 4*c4+0];
                s.y = gr[4*c4+1] + bout[v0 + 4*c4+1];
                s.z = gr[4*c4+2] + bout[v0 + 4*c4+2];
                s.w = gr[4*c4+3] + bout[v0 + 4*c4+3];
                *(float4*)(op + 4*c4) = s;
            }
        }
        __syncthreads();
    }
}

extern "C" void kernel_launch(void* const* d_in, const int* in_sizes, int n_in,
                              void* d_out, int out_size) {
    (void)in_sizes; (void)n_in; (void)out_size;
    prep_w<<<2048, 256>>>((const float*)d_in[4], (const float*)d_in[5]);
    prep_wo<<<2048, 256>>>((const float*)d_in[8]);
    prep_e<<<2048, 256>>>((const int*)d_in[0], (const float*)d_in[3]);
    cudaFuncSetAttribute(lstm_mma, cudaFuncAttributeMaxDynamicSharedMemorySize, SMEM_TOTAL);
    lstm_mma<<<NCTA, NTHR, SMEM_TOTAL>>>(
        (const float*)d_in[1],   // h0
        (const float*)d_in[2],   // c0
        (const float*)d_in[6],   // b_ih
        (const float*)d_in[7],   // b_hh
        (const float*)d_in[9],   // b_out
        (float*)d_out);
}

// round 14
// speedup vs baseline: 7.0212x; 1.0070x over previous
#include <cuda_runtime.h>
#include <cuda_fp16.h>
#include <math.h>
#include <stdint.h>

#define LL 5
#define BB 256
#define HH 512
#define GG 2048
#define SSTEPS 128
#define VV 32000
#define KTOT 1024

#define NCTA 128
#define NTHR 512
#define KC 64          // k elems per chunk (64 fp16 = 128B row = SW128 atom)
#define NCHL 8         // chunks per half-K layer GEMM (K=512 per CTA)
#define NCHO 8         // chunks per output GEMM (K=512)
#define NSTG 4         // cp.async pipeline stages

// dynamic SMEM layout (bytes)
#define SM_BIAS  128   // 5*64 floats
#define SM_TBASE 2048
#define SM_BUF   24576 // A 16K | W 8K
#define OFF_A 0
#define OFF_W 16384
#define SM_GS  (SM_TBASE + NSTG*SM_BUF)        // 100352 (output-GEMM epilogue only)
#define GS_STRIDE 66
#define SMEM_TOTAL (SM_GS + 128*GS_STRIDE*4)   // 134144

// ---- persistent device scratch ----
__device__ __align__(16) __half g_w[LL*GG*KTOT];
__device__ __align__(16) __half g_wo[(size_t)VV*HH];
__device__ __align__(16) __half g_e[(size_t)SSTEPS*BB*HH];
__device__ __align__(16) __half g_h[2*LL*BB*HH];
__device__ float    g_c[(size_t)LL*BB*HH];
__device__ __align__(16) float g_part[(size_t)2*2*32*NTHR*LL*16];  // [kh][mq][nb][tid][cell][16]
__device__ unsigned g_pairflag[2*32];                              // [mq][nb]
__device__ unsigned g_bar_count;
__device__ unsigned g_bar_gen;

// ================= helpers =================
#define SWZ128(o) ((o) ^ (((o) >> 3) & 0x70))

__device__ __forceinline__ uint32_t smem_u32(const void* p) {
    uint32_t a;
    asm("{ .reg .u64 t; cvta.to.shared.u64 t, %1; cvt.u32.u64 %0, t; }" : "=r"(a) : "l"(p));
    return a;
}
__device__ __forceinline__ void cp16(uint32_t d, const void* s) {
    asm volatile("cp.async.cg.shared.global [%0], [%1], 16;" :: "r"(d), "l"(s));
}
__device__ __forceinline__ void cp_commit() { asm volatile("cp.async.commit_group;" ::: "memory"); }
__device__ __forceinline__ void cp_wait2()  { asm volatile("cp.async.wait_group 2;" ::: "memory"); }
__device__ __forceinline__ void cp_wait1()  { asm volatile("cp.async.wait_group 1;" ::: "memory"); }
__device__ __forceinline__ void cp_wait0()  { asm volatile("cp.async.wait_group 0;" ::: "memory"); }

__device__ __forceinline__ void ldsm4(uint32_t* r, uint32_t a) {
    asm volatile("ldmatrix.sync.aligned.m8n8.x4.shared.b16 {%0,%1,%2,%3}, [%4];"
        : "=r"(r[0]), "=r"(r[1]), "=r"(r[2]), "=r"(r[3]) : "r"(a));
}
__device__ __forceinline__ void mma16816(float* d, const uint32_t* a, const uint32_t* b) {
    asm volatile("mma.sync.aligned.m16n8k16.row.col.f32.f16.f16.f32 "
        "{%0,%1,%2,%3}, {%4,%5,%6,%7}, {%8,%9}, {%0,%1,%2,%3};"
        : "+f"(d[0]), "+f"(d[1]), "+f"(d[2]), "+f"(d[3])
        : "r"(a[0]), "r"(a[1]), "r"(a[2]), "r"(a[3]), "r"(b[0]), "r"(b[1]));
}
__device__ __forceinline__ float4 ldcg4(const float* p) {
    float4 v;
    asm volatile("ld.global.cg.v4.f32 {%0,%1,%2,%3}, [%4];"
        : "=f"(v.x), "=f"(v.y), "=f"(v.z), "=f"(v.w) : "l"(p));
    return v;
}

__device__ __forceinline__ float sigf(float v)   { return 1.0f / (1.0f + __expf(-v)); }
__device__ __forceinline__ float tanhft(float v) { return 2.0f / (1.0f + __expf(-2.0f * v)) - 1.0f; }

__device__ __forceinline__ void grid_sync() {
    __syncthreads();
    if (threadIdx.x == 0) {
        __threadfence();
        unsigned gen = *((volatile unsigned*)&g_bar_gen);
        if (atomicAdd(&g_bar_count, 1u) == NCTA - 1u) {
            atomicExch(&g_bar_count, 0u);
            __threadfence();
            atomicAdd(&g_bar_gen, 1u);
        } else {
            while (*((volatile unsigned*)&g_bar_gen) == gen) { __nanosleep(32); }
        }
        __threadfence();
    }
    __syncthreads();
}

// cp.async one chunk (512 threads): A 128x64 fp16 + W 64x64 fp16, SW128 swizzled
__device__ __forceinline__ void issue_chunk(uint32_t tb,
    const __half* a, const __half* w, int wstride, int tid)
{
    #pragma unroll
    for (int j = 0; j < 2; ++j) {
        int g = tid + NTHR * j, m = g >> 3, q = g & 7;
        uint32_t so = SWZ128((uint32_t)(m * 128 + q * 16));
        cp16(tb + OFF_A + so, a + (size_t)m * HH + q * 8);
    }
    {
        int m = tid >> 3, q = tid & 7;
        uint32_t so = SWZ128((uint32_t)(m * 128 + q * 16));
        cp16(tb + OFF_W + so, w + (size_t)m * wstride + q * 8);
    }
    cp_commit();
}

// compute one resident chunk (buffer tb) into d
__device__ __forceinline__ void compute_chunk(float d[2][2][4], uint32_t tb,
    const uint32_t* arow128, uint32_t brow128, int mask, int a_kb, int b_kb)
{
    #pragma unroll
    for (int s = 0; s < 4; ++s) {
        uint32_t a_[2][4], w_[4];
        const uint32_t akx = (uint32_t)((32 * s + a_kb) ^ mask);
        const uint32_t bkx = (uint32_t)((32 * s + b_kb) ^ mask);
        #pragma unroll
        for (int mi = 0; mi < 2; ++mi)
            ldsm4(a_[mi], tb + OFF_A + arow128[mi] + akx);
        ldsm4(w_, tb + OFF_W + brow128 + bkx);
        #pragma unroll
        for (int mi = 0; mi < 2; ++mi)
            #pragma unroll
            for (int h = 0; h < 2; ++h)
                mma16816(d[mi][h], a_[mi], &w_[h * 2]);
    }
}

// standalone GEMM (output stage): 4-stage pipelined fp16 HMMA, D(128x64) in regs
__device__ void gemm_mma(float d[2][2][4], uint32_t sb, int tid, int nch,
    const __half* a0, const __half* w0, int wstride,
    const uint32_t* arow128, uint32_t brow128, int mask, int a_kb, int b_kb)
{
    #pragma unroll
    for (int mi = 0; mi < 2; ++mi)
        #pragma unroll
        for (int ni = 0; ni < 2; ++ni)
            #pragma unroll
            for (int r = 0; r < 4; ++r) d[mi][ni][r] = 0.0f;
    #pragma unroll
    for (int p = 0; p < NSTG - 1; ++p)
        if (p < nch)
            issue_chunk(sb + SM_TBASE + p * SM_BUF, a0 + p * KC, w0 + p * KC, wstride, tid);
    #pragma unroll 1
    for (int c = 0; c < nch; ++c) {
        const int rem = nch - 1 - c;
        if (rem >= 2) cp_wait2(); else if (rem == 1) cp_wait1(); else cp_wait0();
        __syncthreads();
        if (c + NSTG - 1 < nch) {
            const int c2 = c + NSTG - 1;
            issue_chunk(sb + SM_TBASE + (c2 & (NSTG - 1)) * SM_BUF,
                        a0 + c2 * KC, w0 + c2 * KC, wstride, tid);
        }
        compute_chunk(d, sb + SM_TBASE + (c & (NSTG - 1)) * SM_BUF,
                      arow128, brow128, mask, a_kb, b_kb);
    }
}

__device__ __forceinline__ void store_gates(float* gs, const float d[2][2][4], int tid) {
    const int wid = tid >> 5, lane = tid & 31;
    const int wm = wid & 3, wn = wid >> 2;
    const int trow = wm * 32 + (lane >> 2);
    const int tcol = wn * 16 + (lane & 3) * 2;
    #pragma unroll
    for (int mi = 0; mi < 2; ++mi)
        #pragma unroll
        for (int ni = 0; ni < 2; ++ni) {
            const int r0 = trow + mi * 16, cc = tcol + ni * 8;
            *(float2*)(gs + r0 * GS_STRIDE + cc)       = make_float2(d[mi][ni][0], d[mi][ni][1]);
            *(float2*)(gs + (r0 + 8) * GS_STRIDE + cc) = make_float2(d[mi][ni][2], d[mi][ni][3]);
        }
}

// ================= prep kernels =================
// Column permutation within each 64-col tile so that a thread's accumulator quad
// {tc, tc+1, tc+8, tc+9} is exactly gates {i,f,g,o} of one unit:
//   gate(c) = (c&1) | ((c>>3 & 1)<<1),  unit(c) = ((c>>1)&3) | ((c>>4)<<2)
__global__ void prep_w(const float* __restrict__ Wih, const float* __restrict__ Whh) {
    for (int idx = blockIdx.x * blockDim.x + threadIdx.x; idx < LL * GG * KTOT; idx += gridDim.x * blockDim.x) {
        int k = idx & 1023, n = (idx >> 10) & 2047, l = idx >> 21;
        int gate = (n & 1) | (((n >> 3) & 1) << 1);
        int unit = ((n >> 1) & 3) | (((n >> 4) & 3) << 2);
        int src = gate * HH + (n >> 6) * 16 + unit;
        float v = (k < HH) ? Wih[((size_t)l * GG + src) * HH + k]
                           : Whh[((size_t)l * GG + src) * HH + (k - HH)];
        g_w[idx] = __float2half(v);
    }
}
__global__ void prep_wo(const float* __restrict__ Wout) {
    for (size_t idx = blockIdx.x * blockDim.x + threadIdx.x; idx < (size_t)VV * HH; idx += (size_t)gridDim.x * blockDim.x)
        g_wo[idx] = __float2half(Wout[idx]);
}
__global__ void prep_e(const int* __restrict__ x, const float* __restrict__ emb) {
    for (int idx = blockIdx.x * blockDim.x + threadIdx.x; idx < SSTEPS * BB * HH; idx += gridDim.x * blockDim.x) {
        int k = idx & 511, b = (idx >> 9) & 255, t = idx >> 17;
        int tok = x[t * BB + b];   // torch .view(S,B,-1) reinterpretation
        g_e[idx] = __float2half(emb[(size_t)tok * HH + k]);
    }
}

// ================= main persistent kernel =================
__global__ void __launch_bounds__(NTHR, 1)
lstm_mma(const float* __restrict__ h0, const float* __restrict__ c0,
         const float* __restrict__ bih, const float* __restrict__ bhh,
         const float* __restrict__ bout, float* __restrict__ out)
{
    extern __shared__ __align__(1024) char smem[];
    const uint32_t sb = smem_u32(smem);
    const int tid = threadIdx.x, bid = blockIdx.x;
    const int kh = bid & 1;           // K half
    const int nb = (bid >> 1) & 31;   // N tile (64 gate cols = 16 units)
    const int mq = bid >> 6;          // batch half (128 rows)

    const int wid = tid >> 5, lane = tid & 31;
    const int wm = wid & 3, wn = wid >> 2;
    const int mask = (lane & 7) << 4;
    const int a_row = ((lane >> 3) & 1) * 8 + (lane & 7);
    const int a_kb  = ((lane >> 4) & 1) * 16;
    const int b_row = ((lane >> 4) & 1) * 8 + (lane & 7);
    const int b_kb  = ((lane >> 3) & 1) * 16;
    uint32_t arow128[2];
    #pragma unroll
    for (int i = 0; i < 2; ++i)
        arow128[i] = (uint32_t)((wm * 32 + i * 16 + a_row) * 128);
    const uint32_t brow128 = (uint32_t)((wn * 16 + b_row) * 128);
    const int trow = wm * 32 + (lane >> 2);
    const int tc   = wn * 16 + (lane & 3) * 2;
    const int unit = (lane & 3) + 4 * wn;                     // 0..15
    const bool act = (kh == 0) ? (wm < 2) : (wm >= 2);        // own 64-row half

    float* bias_s = (float*)(smem + SM_BIAS);
    float* gs     = (float*)(smem + SM_GS);

    for (int j = tid; j < LL * 64; j += NTHR) {
        int l = j >> 6, c = j & 63;
        int gate = (c & 1) | (((c >> 3) & 1) << 1);
        int un   = ((c >> 1) & 3) | (((c >> 4) & 3) << 2);
        int gi = l * GG + gate * HH + nb * 16 + un;
        bias_s[j] = bih[gi] + bhh[gi];
    }
    for (int j = tid; j < LL * 64 * 16; j += NTHR) {
        int l = j >> 10, r = (j >> 4) & 63, u = j & 15;
        size_t idx = ((size_t)l * BB + mq * 128 + kh * 64 + r) * HH + nb * 16 + u;
        g_c[idx] = c0[idx];
    }
    for (int i = bid * NTHR + tid; i < LL * BB * HH; i += NCTA * NTHR)
        g_h[LL * BB * HH + i] = __float2half(h0[i]);
    if (kh == 0 && tid == 0) atomicExch(&g_pairflag[mq * 32 + nb], 0u);
    grid_sync();

    const size_t row0 = (size_t)(mq * 128) * HH;
    float d[2][2][4];
    float* mypart       = g_part + ((size_t)((kh * 2 + mq) * 32 + nb) * NTHR + tid) * (LL * 16);
    const float* thpart = g_part + ((size_t)(((kh ^ 1) * 2 + mq) * 32 + nb) * NTHR + tid) * (LL * 16);
    unsigned* pflag = &g_pairflag[mq * 32 + nb];
    unsigned pair_exp = 0;

    // ======== wavefront over diagonals dg = t + l ========
    #pragma unroll 1
    for (int dg = 0; dg < SSTEPS + LL - 1; ++dg) {
        const int l_lo = (dg > SSTEPS - 1) ? (dg - (SSTEPS - 1)) : 0;
        const int l_hi = (dg < LL - 1) ? dg : (LL - 1);
        const int ncells = l_hi - l_lo + 1;
        const int total = ncells * NCHL;

        // cell pointer resolver (weights + A source for chunk base)
        #define CELLPTR(cc, A, W) do { \
            const int _l = l_lo + (cc); const int _t = dg - _l; \
            const int _cur = _t & 1, _prev = _cur ^ 1; \
            if (kh == 0) { \
                if (_l == 0) (A) = g_e + (size_t)_t * BB * HH + row0; \
                else         (A) = g_h + ((size_t)_cur * LL + (_l - 1)) * BB * HH + row0; \
            } else { \
                (A) = g_h + ((size_t)_prev * LL + _l) * BB * HH + row0; \
            } \
            (W) = g_w + ((size_t)_l * GG + nb * 64) * KTOT + kh * (NCHL * KC); \
        } while (0)

        // ---- phase 1: ONE continuous pipeline across all cells of the diagonal ----
        {
            const __half *ap, *wp;
            #pragma unroll
            for (int p = 0; p < NSTG - 1; ++p)
                if (p < total) {
                    CELLPTR(p >> 3, ap, wp);
                    issue_chunk(sb + SM_TBASE + p * SM_BUF,
                                ap + (p & 7) * KC, wp + (p & 7) * KC, KTOT, tid);
                }
            #pragma unroll
            for (int mi = 0; mi < 2; ++mi)
                #pragma unroll
                for (int ni = 0; ni < 2; ++ni)
                    #pragma unroll
                    for (int r = 0; r < 4; ++r) d[mi][ni][r] = 0.0f;

            #pragma unroll 1
            for (int g = 0; g < total; ++g) {
                const int rem = total - 1 - g;
                if (rem >= 2) cp_wait2(); else if (rem == 1) cp_wait1(); else cp_wait0();
                __syncthreads();
                if (g + NSTG - 1 < total) {
                    const int g2 = g + NSTG - 1;
                    CELLPTR(g2 >> 3, ap, wp);
                    issue_chunk(sb + SM_TBASE + (g2 & (NSTG - 1)) * SM_BUF,
                                ap + (g2 & 7) * KC, wp + (g2 & 7) * KC, KTOT, tid);
                }
                compute_chunk(d, sb + SM_TBASE + (g & (NSTG - 1)) * SM_BUF,
                              arow128, brow128, mask, a_kb, b_kb);
                if ((g & 7) == 7) {   // cell boundary: dump partials, rezero accums
                    float* mp = mypart + (g >> 3) * 16;
                    #pragma unroll
                    for (int mi = 0; mi < 2; ++mi)
                        #pragma unroll
                        for (int ni = 0; ni < 2; ++ni) {
                            *(float4*)(mp + (mi * 2 + ni) * 4) = *(const float4*)d[mi][ni];
                            d[mi][ni][0] = d[mi][ni][1] = d[mi][ni][2] = d[mi][ni][3] = 0.0f;
                        }
                }
            }
        }

        // ---- exchange: one flag per diagonal ----
        __threadfence();
        __syncthreads();
        if (tid == 0) atomicAdd(pflag, 1u);
        pair_exp += 2;
        if (tid == 0) {
            while (*((volatile unsigned*)pflag) < pair_exp) { __nanosleep(20); }
        }
        __syncthreads();

        // ---- phase 2: in-register combine + activation (no smem, no syncs) ----
        if (act) {
            #pragma unroll 1
            for (int cc = 0; cc < ncells; ++cc) {
                const int l = l_lo + cc;
                const int t = dg - l;
                const int cur = t & 1;
                const int ci = cc * 16;
                #pragma unroll
                for (int mi = 0; mi < 2; ++mi)
                    #pragma unroll
                    for (int ni = 0; ni < 2; ++ni) {
                        const float4 m4 = *(const float4*)(mypart + ci + (mi * 2 + ni) * 4);
                        const float4 p4 = ldcg4(thpart + ci + (mi * 2 + ni) * 4);
                        d[mi][ni][0] = m4.x + p4.x; d[mi][ni][1] = m4.y + p4.y;
                        d[mi][ni][2] = m4.z + p4.z; d[mi][ni][3] = m4.w + p4.w;
                    }
                const float b0 = bias_s[l * 64 + tc];
                const float b1 = bias_s[l * 64 + tc + 1];
                const float b2 = bias_s[l * 64 + tc + 8];
                const float b3 = bias_s[l * 64 + tc + 9];
                #pragma unroll
                for (int mi = 0; mi < 2; ++mi)
                    #pragma unroll
                    for (int rr = 0; rr < 2; ++rr) {
                        const int R = trow + mi * 16 + rr * 8;        // 0..127
                        const float gi = d[mi][0][rr * 2 + 0] + b0;
                        const float gf = d[mi][0][rr * 2 + 1] + b1;
                        const float gg = d[mi][1][rr * 2 + 0] + b2;
                        const float go = d[mi][1][rr * 2 + 1] + b3;
                        const int b = mq * 128 + R;
                        const size_t cidx = ((size_t)l * BB + b) * HH + nb * 16 + unit;
                        const float cn = sigf(gf) * g_c[cidx] + sigf(gi) * tanhft(gg);
                        g_c[cidx] = cn;
                        const float hv = sigf(go) * tanhft(cn);
                        const size_t ho = ((size_t)cur * LL + l) * BB * HH + (size_t)b * HH + nb * 16 + unit;
                        g_h[ho] = __float2half(hv);
                    }
            }
        }
        grid_sync();   // diagonal complete: h visible chip-wide
    }

    // ---- output GEMM: logits 256x32000, K=512 -> 1000 tiles of 128x64 ----
    const size_t hf = ((size_t)((SSTEPS - 1) & 1) * LL + (LL - 1)) * BB * HH;
    #pragma unroll 1
    for (int tt = bid; tt < 1000; tt += NCTA) {
        const int b0 = (tt / 500) * 128;
        const int v0 = (tt % 500) * 64;
        gemm_mma(d, sb, tid, NCHO,
                 g_h + hf + (size_t)b0 * HH, g_wo + (size_t)v0 * HH, HH,
                 arow128, brow128, mask, a_kb, b_kb);
        store_gates(gs, d, tid);
        __syncthreads();
        if (tid < 128) {
            const float* gr = gs + tid * GS_STRIDE;
            float* op = out + (size_t)(b0 + tid) * VV + v0;
            #pragma unroll
            for (int c4 = 0; c4 < 16; ++c4) {
                float4 s;
                s.x = gr[4*c4+0] + bout[v0 + 4*c4+0];
                s.y = gr[4*c4+1] + bout[v0 + 4*c4+1];
                s.z = gr[4*c4+2] + bout[v0 + 4*c4+2];
                s.w = gr[4*c4+3] + bout[v0 + 4*c4+3];
                *(float4*)(op + 4*c4) = s;
            }
        }
        __syncthreads();
    }
}

extern "C" void kernel_launch(void* const* d_in, const int* in_sizes, int n_in,
                              void* d_out, int out_size) {
    (void)in_sizes; (void)n_in; (void)out_size;
    prep_w<<<2048, 256>>>((const float*)d_in[4], (const float*)d_in[5]);
    prep_wo<<<2048, 256>>>((const float*)d_in[8]);
    prep_e<<<2048, 256>>>((const int*)d_in[0], (const float*)d_in[3]);
    cudaFuncSetAttribute(lstm_mma, cudaFuncAttributeMaxDynamicSharedMemorySize, SMEM_TOTAL);
    lstm_mma<<<NCTA, NTHR, SMEM_TOTAL>>>(
        (const float*)d_in[1],   // h0
        (const float*)d_in[2],   // c0
        (const float*)d_in[6],   // b_ih
        (const float*)d_in[7],   // b_hh
        (const float*)d_in[9],   // b_out
        (float*)d_out);
}

// round 15
// speedup vs baseline: 7.5358x; 1.0733x over previous
#include <cuda_runtime.h>
#include <cuda_fp16.h>
#include <math.h>
#include <stdint.h>

#define LL 5
#define BB 256
#define HH 512
#define GG 2048
#define SSTEPS 128
#define VV 32000
#define KTOT 1024

#define NCTA 256
#define NTHR 256
#define KC 64          // k elems per chunk
#define NCHL 8         // chunks per half-K layer GEMM (K=512 per CTA)
#define NCHO 8         // chunks per output GEMM (K=512)
#define NSTG 4         // cp.async pipeline stages

// dynamic SMEM layout (bytes)
#define SM_BIAS  128   // 5*64 floats
#define SM_TBASE 2048
#define SM_BUF   16384 // A 8K (64x64) | W 8K (64x64)
#define OFF_A 0
#define OFF_W 8192
#define SM_GS  (SM_TBASE + NSTG*SM_BUF)        // 67584 (output epilogue only)
#define GS_STRIDE 66
#define SMEM_TOTAL (SM_GS + 64*GS_STRIDE*4)    // 84480 -> 2 CTAs/SM

// ---- persistent device scratch ----
__device__ __align__(16) __half g_w[LL*GG*KTOT];
__device__ __align__(16) __half g_wo[(size_t)VV*HH];
__device__ __align__(16) __half g_e[(size_t)SSTEPS*BB*HH];
__device__ __align__(16) __half g_h[2*LL*BB*HH];
__device__ __align__(16) float g_part[(size_t)2*4*32*NTHR*LL*16];  // [kh][mq][nb][tid][cell][16]
__device__ unsigned g_pairflag[4*32];                              // [mq][nb]
__device__ unsigned g_mq_count[4];
__device__ unsigned g_mq_gen[4];
__device__ unsigned g_bar_count;
__device__ unsigned g_bar_gen;

// ================= helpers =================
#define SWZ128(o) ((o) ^ (((o) >> 3) & 0x70))

__device__ __forceinline__ uint32_t smem_u32(const void* p) {
    uint32_t a;
    asm("{ .reg .u64 t; cvta.to.shared.u64 t, %1; cvt.u32.u64 %0, t; }" : "=r"(a) : "l"(p));
    return a;
}
__device__ __forceinline__ void cp16(uint32_t d, const void* s) {
    asm volatile("cp.async.cg.shared.global [%0], [%1], 16;" :: "r"(d), "l"(s));
}
__device__ __forceinline__ void cp_commit() { asm volatile("cp.async.commit_group;" ::: "memory"); }
__device__ __forceinline__ void cp_wait2()  { asm volatile("cp.async.wait_group 2;" ::: "memory"); }
__device__ __forceinline__ void cp_wait1()  { asm volatile("cp.async.wait_group 1;" ::: "memory"); }
__device__ __forceinline__ void cp_wait0()  { asm volatile("cp.async.wait_group 0;" ::: "memory"); }

__device__ __forceinline__ void ldsm4(uint32_t* r, uint32_t a) {
    asm volatile("ldmatrix.sync.aligned.m8n8.x4.shared.b16 {%0,%1,%2,%3}, [%4];"
        : "=r"(r[0]), "=r"(r[1]), "=r"(r[2]), "=r"(r[3]) : "r"(a));
}
__device__ __forceinline__ void mma16816(float* d, const uint32_t* a, const uint32_t* b) {
    asm volatile("mma.sync.aligned.m16n8k16.row.col.f32.f16.f16.f32 "
        "{%0,%1,%2,%3}, {%4,%5,%6,%7}, {%8,%9}, {%0,%1,%2,%3};"
        : "+f"(d[0]), "+f"(d[1]), "+f"(d[2]), "+f"(d[3])
        : "r"(a[0]), "r"(a[1]), "r"(a[2]), "r"(a[3]), "r"(b[0]), "r"(b[1]));
}
__device__ __forceinline__ float4 ldcg4(const float* p) {
    float4 v;
    asm volatile("ld.global.cg.v4.f32 {%0,%1,%2,%3}, [%4];"
        : "=f"(v.x), "=f"(v.y), "=f"(v.z), "=f"(v.w) : "l"(p));
    return v;
}

__device__ __forceinline__ float sigf(float v)   { return 1.0f / (1.0f + __expf(-v)); }
__device__ __forceinline__ float tanhft(float v) { return 2.0f / (1.0f + __expf(-2.0f * v)) - 1.0f; }

// global barrier over all 256 CTAs
__device__ __forceinline__ void grid_sync() {
    __syncthreads();
    if (threadIdx.x == 0) {
        __threadfence();
        unsigned gen = *((volatile unsigned*)&g_bar_gen);
        if (atomicAdd(&g_bar_count, 1u) == NCTA - 1u) {
            atomicExch(&g_bar_count, 0u);
            __threadfence();
            atomicAdd(&g_bar_gen, 1u);
        } else {
            while (*((volatile unsigned*)&g_bar_gen) == gen) { __nanosleep(32); }
        }
        __threadfence();
    }
    __syncthreads();
}
// barrier over the 64 CTAs of one mq group (batch quarters share no data)
__device__ __forceinline__ void mq_sync(int mq) {
    __syncthreads();
    if (threadIdx.x == 0) {
        __threadfence();
        unsigned gen = *((volatile unsigned*)&g_mq_gen[mq]);
        if (atomicAdd(&g_mq_count[mq], 1u) == 63u) {
            atomicExch(&g_mq_count[mq], 0u);
            __threadfence();
            atomicAdd(&g_mq_gen[mq], 1u);
        } else {
            while (*((volatile unsigned*)&g_mq_gen[mq]) == gen) { __nanosleep(32); }
        }
        __threadfence();
    }
    __syncthreads();
}

// cp.async one chunk (256 threads): A 64x64 fp16 + W 64x64 fp16, SW128 swizzled
__device__ __forceinline__ void issue_chunk(uint32_t tb,
    const __half* a, const __half* w, int wstride, int tid)
{
    #pragma unroll
    for (int j = 0; j < 2; ++j) {
        int g = tid + NTHR * j, m = g >> 3, q = g & 7;
        uint32_t so = SWZ128((uint32_t)(m * 128 + q * 16));
        cp16(tb + OFF_A + so, a + (size_t)m * HH + q * 8);
    }
    #pragma unroll
    for (int j = 0; j < 2; ++j) {
        int g = tid + NTHR * j, m = g >> 3, q = g & 7;
        uint32_t so = SWZ128((uint32_t)(m * 128 + q * 16));
        cp16(tb + OFF_W + so, w + (size_t)m * wstride + q * 8);
    }
    cp_commit();
}

// compute one resident chunk into d[4][4]. 8 warps = 4m x 2n, warp tile 16x32.
__device__ __forceinline__ void compute_chunk(float d[4][4], uint32_t tb,
    uint32_t arow128, const uint32_t* brow128, int mask, int a_kb, int b_kb)
{
    #pragma unroll
    for (int s = 0; s < 4; ++s) {
        uint32_t a_[4], w_[2][4];
        const uint32_t akx = (uint32_t)((32 * s + a_kb) ^ mask);
        const uint32_t bkx = (uint32_t)((32 * s + b_kb) ^ mask);
        ldsm4(a_, tb + OFF_A + arow128 + akx);
        #pragma unroll
        for (int nj = 0; nj < 2; ++nj)
            ldsm4(w_[nj], tb + OFF_W + brow128[nj] + bkx);
        #pragma unroll
        for (int nj = 0; nj < 2; ++nj)
            #pragma unroll
            for (int h = 0; h < 2; ++h)
                mma16816(d[nj * 2 + h], a_, &w_[nj][h * 2]);
    }
}

// standalone 4-stage pipelined GEMM (output stage)
__device__ void gemm_mma(float d[4][4], uint32_t sb, int tid, int nch,
    const __half* a0, const __half* w0, int wstride,
    uint32_t arow128, const uint32_t* brow128, int mask, int a_kb, int b_kb)
{
    #pragma unroll
    for (int nf = 0; nf < 4; ++nf)
        #pragma unroll
        for (int r = 0; r < 4; ++r) d[nf][r] = 0.0f;
    #pragma unroll
    for (int p = 0; p < NSTG - 1; ++p)
        if (p < nch)
            issue_chunk(sb + SM_TBASE + p * SM_BUF, a0 + p * KC, w0 + p * KC, wstride, tid);
    #pragma unroll 1
    for (int c = 0; c < nch; ++c) {
        const int rem = nch - 1 - c;
        if (rem >= 2) cp_wait2(); else if (rem == 1) cp_wait1(); else cp_wait0();
        __syncthreads();
        if (c + NSTG - 1 < nch) {
            const int c2 = c + NSTG - 1;
            issue_chunk(sb + SM_TBASE + (c2 & (NSTG - 1)) * SM_BUF,
                        a0 + c2 * KC, w0 + c2 * KC, wstride, tid);
        }
        compute_chunk(d, sb + SM_TBASE + (c & (NSTG - 1)) * SM_BUF,
                      arow128, brow128, mask, a_kb, b_kb);
    }
}

// store accumulators into padded fp32 tile gs[64][GS_STRIDE]
__device__ __forceinline__ void store_gates(float* gs, const float d[4][4], int tid) {
    const int wid = tid >> 5, lane = tid & 31;
    const int wm = wid & 3, wn = wid >> 2;
    const int trow = wm * 16 + (lane >> 2);
    #pragma unroll
    for (int nf = 0; nf < 4; ++nf) {
        const int cc = wn * 32 + nf * 8 + (lane & 3) * 2;
        *(float2*)(gs + trow * GS_STRIDE + cc)       = make_float2(d[nf][0], d[nf][1]);
        *(float2*)(gs + (trow + 8) * GS_STRIDE + cc) = make_float2(d[nf][2], d[nf][3]);
    }
}

// ================= prep kernels =================
// 64-col tile permutation: col c -> gate (c&1)|((c>>3&1)<<1), unit ((c>>1)&3)|((c>>4)<<2)
// => thread accumulator quad {c, c+1, c+8, c+9} = gates {i,f,g,o} of ONE unit.
__global__ void prep_w(const float* __restrict__ Wih, const float* __restrict__ Whh) {
    for (int idx = blockIdx.x * blockDim.x + threadIdx.x; idx < LL * GG * KTOT; idx += gridDim.x * blockDim.x) {
        int k = idx & 1023, n = (idx >> 10) & 2047, l = idx >> 21;
        int gate = (n & 1) | (((n >> 3) & 1) << 1);
        int unit = ((n >> 1) & 3) | (((n >> 4) & 3) << 2);
        int src = gate * HH + (n >> 6) * 16 + unit;
        float v = (k < HH) ? Wih[((size_t)l * GG + src) * HH + k]
                           : Whh[((size_t)l * GG + src) * HH + (k - HH)];
        g_w[idx] = __float2half(v);
    }
}
__global__ void prep_wo(const float* __restrict__ Wout) {
    for (size_t idx = blockIdx.x * blockDim.x + threadIdx.x; idx < (size_t)VV * HH; idx += (size_t)gridDim.x * blockDim.x)
        g_wo[idx] = __float2half(Wout[idx]);
}
__global__ void prep_e(const int* __restrict__ x, const float* __restrict__ emb) {
    for (int idx = blockIdx.x * blockDim.x + threadIdx.x; idx < SSTEPS * BB * HH; idx += gridDim.x * blockDim.x) {
        int k = idx & 511, b = (idx >> 9) & 255, t = idx >> 17;
        int tok = x[t * BB + b];   // torch .view(S,B,-1) reinterpretation
        g_e[idx] = __float2half(emb[(size_t)tok * HH + k]);
    }
}

// ================= main persistent kernel =================
__global__ void __launch_bounds__(NTHR, 2)
lstm_mma(const float* __restrict__ h0, const float* __restrict__ c0,
         const float* __restrict__ bih, const float* __restrict__ bhh,
         const float* __restrict__ bout, float* __restrict__ out)
{
    extern __shared__ __align__(1024) char smem[];
    const uint32_t sb = smem_u32(smem);
    const int tid = threadIdx.x, bid = blockIdx.x;
    const int kh = bid & 1;           // K half
    const int nb = (bid >> 1) & 31;   // N tile (64 gate cols = 16 units)
    const int mq = bid >> 6;          // batch quarter (64 rows)

    const int wid = tid >> 5, lane = tid & 31;
    const int wm = wid & 3, wn = wid >> 2;           // 4m x 2n
    const int mask = (lane & 7) << 4;
    const int a_row = ((lane >> 3) & 1) * 8 + (lane & 7);
    const int a_kb  = ((lane >> 4) & 1) * 16;
    const int b_row = ((lane >> 4) & 1) * 8 + (lane & 7);
    const int b_kb  = ((lane >> 3) & 1) * 16;
    const uint32_t arow128 = (uint32_t)((wm * 16 + a_row) * 128);
    uint32_t brow128[2];
    #pragma unroll
    for (int nj = 0; nj < 2; ++nj)
        brow128[nj] = (uint32_t)((wn * 32 + nj * 16 + b_row) * 128);
    const int trow = wm * 16 + (lane >> 2);
    const int actrow = trow + kh * 8;                // row this CTA activates

    float* bias_s = (float*)(smem + SM_BIAS);
    float* gs     = (float*)(smem + SM_GS);

    for (int j = tid; j < LL * 64; j += NTHR) {
        int l = j >> 6, c = j & 63;
        int gate = (c & 1) | (((c >> 3) & 1) << 1);
        int un   = ((c >> 1) & 3) | (((c >> 4) & 3) << 2);
        int gi = l * GG + gate * HH + nb * 16 + un;
        bias_s[j] = bih[gi] + bhh[gi];
    }
    // c-state in registers: cst[l][q], (row=actrow, unit depends on q)
    int unitq[2];
    #pragma unroll
    for (int q = 0; q < 2; ++q)
        unitq[q] = (lane & 3) + 4 * (wn * 2 + q);
    float cst[LL][2];
    #pragma unroll
    for (int l = 0; l < LL; ++l)
        #pragma unroll
        for (int q = 0; q < 2; ++q)
            cst[l][q] = c0[((size_t)l * BB + mq * 64 + actrow) * HH + nb * 16 + unitq[q]];
    // h0 -> fp16 (cooperative across all CTAs)
    for (int i = bid * NTHR + tid; i < LL * BB * HH; i += NCTA * NTHR)
        g_h[LL * BB * HH + i] = __float2half(h0[i]);
    if (kh == 0 && tid == 0) atomicExch(&g_pairflag[mq * 32 + nb], 0u);
    grid_sync();

    const size_t row0 = (size_t)(mq * 64) * HH;
    float d[4][4];
    float* mypart       = g_part + ((size_t)((kh * 4 + mq) * 32 + nb) * NTHR + tid) * (LL * 16);
    const float* thpart = g_part + ((size_t)(((kh ^ 1) * 4 + mq) * 32 + nb) * NTHR + tid) * (LL * 16);
    unsigned* pflag = &g_pairflag[mq * 32 + nb];
    unsigned pair_exp = 0;

    // ======== wavefront over diagonals dg = t + l (per-mq groups drift freely) ========
    #pragma unroll 1
    for (int dg = 0; dg < SSTEPS + LL - 1; ++dg) {
        const int l_lo = (dg > SSTEPS - 1) ? (dg - (SSTEPS - 1)) : 0;
        const int l_hi = (dg < LL - 1) ? dg : (LL - 1);
        const int ncells = l_hi - l_lo + 1;
        const int total = ncells * NCHL;

        #define CELLPTR(cc, A, W) do { \
            const int _l = l_lo + (cc); const int _t = dg - _l; \
            const int _cur = _t & 1, _prev = _cur ^ 1; \
            if (kh == 0) { \
                if (_l == 0) (A) = g_e + (size_t)_t * BB * HH + row0; \
                else         (A) = g_h + ((size_t)_cur * LL + (_l - 1)) * BB * HH + row0; \
            } else { \
                (A) = g_h + ((size_t)_prev * LL + _l) * BB * HH + row0; \
            } \
            (W) = g_w + ((size_t)_l * GG + nb * 64) * KTOT + kh * (NCHL * KC); \
        } while (0)

        // ---- phase 1: ONE continuous pipeline across all cells ----
        {
            const __half *ap, *wp;
            #pragma unroll
            for (int p = 0; p < NSTG - 1; ++p)
                if (p < total) {
                    CELLPTR(p >> 3, ap, wp);
                    issue_chunk(sb + SM_TBASE + p * SM_BUF,
                                ap + (p & 7) * KC, wp + (p & 7) * KC, KTOT, tid);
                }
            #pragma unroll
            for (int nf = 0; nf < 4; ++nf)
                #pragma unroll
                for (int r = 0; r < 4; ++r) d[nf][r] = 0.0f;

            #pragma unroll 1
            for (int g = 0; g < total; ++g) {
                const int rem = total - 1 - g;
                if (rem >= 2) cp_wait2(); else if (rem == 1) cp_wait1(); else cp_wait0();
                __syncthreads();
                if (g + NSTG - 1 < total) {
                    const int g2 = g + NSTG - 1;
                    CELLPTR(g2 >> 3, ap, wp);
                    issue_chunk(sb + SM_TBASE + (g2 & (NSTG - 1)) * SM_BUF,
                                ap + (g2 & 7) * KC, wp + (g2 & 7) * KC, KTOT, tid);
                }
                compute_chunk(d, sb + SM_TBASE + (g & (NSTG - 1)) * SM_BUF,
                              arow128, brow128, mask, a_kb, b_kb);
                if ((g & 7) == 7) {   // cell boundary: dump partials, rezero
                    float* mp = mypart + (g >> 3) * 16;
                    #pragma unroll
                    for (int nf = 0; nf < 4; ++nf) {
                        *(float4*)(mp + nf * 4) = *(const float4*)d[nf];
                        d[nf][0] = d[nf][1] = d[nf][2] = d[nf][3] = 0.0f;
                    }
                }
            }
        }

        // ---- exchange: one flag per diagonal (pair-local) ----
        __threadfence();
        __syncthreads();
        if (tid == 0) atomicAdd(pflag, 1u);
        pair_exp += 2;
        if (tid == 0) {
            while (*((volatile unsigned*)pflag) < pair_exp) { __nanosleep(20); }
        }
        __syncthreads();

        // ---- phase 2: in-register combine + activation (rows of parity kh) ----
        #pragma unroll 1
        for (int cc = 0; cc < ncells; ++cc) {
            const int l = l_lo + cc;
            const int t = dg - l;
            const int cur = t & 1;
            const int ci = cc * 16;
            float f[4][4];
            #pragma unroll
            for (int nf = 0; nf < 4; ++nf) {
                const float4 m4 = *(const float4*)(mypart + ci + nf * 4);
                const float4 p4 = ldcg4(thpart + ci + nf * 4);
                f[nf][0] = m4.x + p4.x; f[nf][1] = m4.y + p4.y;
                f[nf][2] = m4.z + p4.z; f[nf][3] = m4.w + p4.w;
            }
            const int b = mq * 64 + actrow;
            #pragma unroll
            for (int q = 0; q < 2; ++q) {
                const int cb = wn * 32 + q * 16 + (lane & 3) * 2;
                const float gi = f[q * 2 + 0][kh * 2 + 0] + bias_s[l * 64 + cb];
                const float gf = f[q * 2 + 0][kh * 2 + 1] + bias_s[l * 64 + cb + 1];
                const float gg = f[q * 2 + 1][kh * 2 + 0] + bias_s[l * 64 + cb + 8];
                const float go = f[q * 2 + 1][kh * 2 + 1] + bias_s[l * 64 + cb + 9];
                const float cn = sigf(gf) * cst[l][q] + sigf(gi) * tanhft(gg);
                cst[l][q] = cn;
                const float hv = sigf(go) * tanhft(cn);
                const size_t ho = ((size_t)cur * LL + l) * BB * HH + (size_t)b * HH + nb * 16 + unitq[q];
                g_h[ho] = __float2half(hv);
            }
        }
        mq_sync(mq);   // diagonal complete within this batch quarter
    }

    grid_sync();   // all quarters done before cross-quarter output reads

    // ---- output GEMM: logits 256x32000, K=512 -> 4 x 500 = 2000 tiles of 64x64 ----
    const size_t hf = ((size_t)((SSTEPS - 1) & 1) * LL + (LL - 1)) * BB * HH;
    #pragma unroll 1
    for (int tt = bid; tt < 2000; tt += NCTA) {
        const int b0 = (tt / 500) * 64;
        const int v0 = (tt % 500) * 64;
        gemm_mma(d, sb, tid, NCHO,
                 g_h + hf + (size_t)b0 * HH, g_wo + (size_t)v0 * HH, HH,
                 arow128, brow128, mask, a_kb, b_kb);
        store_gates(gs, d, tid);
        __syncthreads();
        {   // 256 threads: row = tid>>2, 16 cols each
            const int row = tid >> 2;
            const int c0c = (tid & 3) * 16;
            const float* gr = gs + row * GS_STRIDE + c0c;
            float* op = out + (size_t)(b0 + row) * VV + v0 + c0c;
            #pragma unroll
            for (int c4 = 0; c4 < 4; ++c4) {
                float4 s;
                s.x = gr[4*c4+0] + bout[v0 + c0c + 4*c4+0];
                s.y = gr[4*c4+1] + bout[v0 + c0c + 4*c4+1];
                s.z = gr[4*c4+2] + bout[v0 + c0c + 4*c4+2];
                s.w = gr[4*c4+3] + bout[v0 + c0c + 4*c4+3];
                *(float4*)(op + 4*c4) = s;
            }
        }
        __syncthreads();
    }
}

extern "C" void kernel_launch(void* const* d_in, const int* in_sizes, int n_in,
                              void* d_out, int out_size) {
    (void)in_sizes; (void)n_in; (void)out_size;
    prep_w<<<2048, 256>>>((const float*)d_in[4], (const float*)d_in[5]);
    prep_wo<<<2048, 256>>>((const float*)d_in[8]);
    prep_e<<<2048, 256>>>((const int*)d_in[0], (const float*)d_in[3]);
    cudaFuncSetAttribute(lstm_mma, cudaFuncAttributeMaxDynamicSharedMemorySize, SMEM_TOTAL);
    lstm_mma<<<NCTA, NTHR, SMEM_TOTAL>>>(
        (const float*)d_in[1],   // h0
        (const float*)d_in[2],   // c0
        (const float*)d_in[6],   // b_ih
        (const float*)d_in[7],   // b_hh
        (const float*)d_in[9],   // b_out
        (float*)d_out);
}

// round 16
// speedup vs baseline: 7.8760x; 1.0451x over previous
#include <cuda_runtime.h>
#include <cuda_fp16.h>
#include <math.h>
#include <stdint.h>

#define LL 5
#define BB 256
#define HH 512
#define GG 2048
#define SSTEPS 128
#define VV 32000
#define KTOT 1024

#define NCTA 296       // exactly 2 CTAs per SM on 148 SMs
#define NTHR 256
#define KC 64
#define NCHL 8         // chunks per task (K=512)
#define NCHO 8
#define NSTG 4
#define NDIAG (SSTEPS + LL - 1)   // 132

// dynamic SMEM layout (bytes)
#define SM_TBASE 2048
#define SM_BUF   16384 // A 8K (64x64 fp16) | W 8K (64x64 fp16)
#define OFF_A 0
#define OFF_W 8192
#define SM_GS  (SM_TBASE + NSTG*SM_BUF)        // 67584 (output epilogue only)
#define GS_STRIDE 66
#define SMEM_TOTAL (SM_GS + 64*GS_STRIDE*4)    // 84480 -> 2 CTAs/SM

// ---- persistent device scratch ----
__device__ __align__(16) __half g_w[LL*GG*KTOT];
__device__ __align__(16) __half g_wo[(size_t)VV*HH];
__device__ __align__(16) __half g_e[(size_t)SSTEPS*BB*HH];
__device__ __align__(16) __half g_h[2*LL*BB*HH];
__device__ float    g_c[(size_t)LL*BB*HH];
__device__ float    g_bias[LL*GG];
__device__ __align__(16) float g_part[(size_t)1280*NTHR*16];   // [task id][tid][16]
__device__ unsigned g_tick[NDIAG];
__device__ unsigned g_done[NDIAG*640];
__device__ unsigned g_bar_count;
__device__ unsigned g_bar_gen;

// ================= helpers =================
#define SWZ128(o) ((o) ^ (((o) >> 3) & 0x70))

__device__ __forceinline__ uint32_t smem_u32(const void* p) {
    uint32_t a;
    asm("{ .reg .u64 t; cvta.to.shared.u64 t, %1; cvt.u32.u64 %0, t; }" : "=r"(a) : "l"(p));
    return a;
}
__device__ __forceinline__ void cp16(uint32_t d, const void* s) {
    asm volatile("cp.async.cg.shared.global [%0], [%1], 16;" :: "r"(d), "l"(s));
}
__device__ __forceinline__ void cp_commit() { asm volatile("cp.async.commit_group;" ::: "memory"); }
__device__ __forceinline__ void cp_wait2()  { asm volatile("cp.async.wait_group 2;" ::: "memory"); }
__device__ __forceinline__ void cp_wait1()  { asm volatile("cp.async.wait_group 1;" ::: "memory"); }
__device__ __forceinline__ void cp_wait0()  { asm volatile("cp.async.wait_group 0;" ::: "memory"); }

__device__ __forceinline__ void ldsm4(uint32_t* r, uint32_t a) {
    asm volatile("ldmatrix.sync.aligned.m8n8.x4.shared.b16 {%0,%1,%2,%3}, [%4];"
        : "=r"(r[0]), "=r"(r[1]), "=r"(r[2]), "=r"(r[3]) : "r"(a));
}
__device__ __forceinline__ void mma16816(float* d, const uint32_t* a, const uint32_t* b) {
    asm volatile("mma.sync.aligned.m16n8k16.row.col.f32.f16.f16.f32 "
        "{%0,%1,%2,%3}, {%4,%5,%6,%7}, {%8,%9}, {%0,%1,%2,%3};"
        : "+f"(d[0]), "+f"(d[1]), "+f"(d[2]), "+f"(d[3])
        : "r"(a[0]), "r"(a[1]), "r"(a[2]), "r"(a[3]), "r"(b[0]), "r"(b[1]));
}
__device__ __forceinline__ float4 ldcg4(const float* p) {
    float4 v;
    asm volatile("ld.global.cg.v4.f32 {%0,%1,%2,%3}, [%4];"
        : "=f"(v.x), "=f"(v.y), "=f"(v.z), "=f"(v.w) : "l"(p));
    return v;
}

__device__ __forceinline__ float sigf(float v)   { return 1.0f / (1.0f + __expf(-v)); }
__device__ __forceinline__ float tanhft(float v) { return 2.0f / (1.0f + __expf(-2.0f * v)) - 1.0f; }

__device__ __forceinline__ void grid_sync() {
    __syncthreads();
    if (threadIdx.x == 0) {
        __threadfence();
        unsigned gen = *((volatile unsigned*)&g_bar_gen);
        if (atomicAdd(&g_bar_count, 1u) == NCTA - 1u) {
            atomicExch(&g_bar_count, 0u);
            __threadfence();
            atomicAdd(&g_bar_gen, 1u);
        } else {
            while (*((volatile unsigned*)&g_bar_gen) == gen) { __nanosleep(32); }
        }
        __threadfence();
    }
    __syncthreads();
}

// cp.async one chunk (256 threads): A 64x64 fp16 + W 64x64 fp16, SW128 swizzled
__device__ __forceinline__ void issue_chunk(uint32_t tb,
    const __half* a, const __half* w, int wstride, int tid)
{
    #pragma unroll
    for (int j = 0; j < 2; ++j) {
        int g = tid + NTHR * j, m = g >> 3, q = g & 7;
        uint32_t so = SWZ128((uint32_t)(m * 128 + q * 16));
        cp16(tb + OFF_A + so, a + (size_t)m * HH + q * 8);
    }
    #pragma unroll
    for (int j = 0; j < 2; ++j) {
        int g = tid + NTHR * j, m = g >> 3, q = g & 7;
        uint32_t so = SWZ128((uint32_t)(m * 128 + q * 16));
        cp16(tb + OFF_W + so, w + (size_t)m * wstride + q * 8);
    }
    cp_commit();
}

// task id encodes (cell<<8)|(kh<<7)|(mq<<5)|nb
__device__ __forceinline__ void issue_task_chunk(uint32_t tb, int id, int k,
                                                 int dg, int l_lo, int tid)
{
    const int nb = id & 31, mqv = (id >> 5) & 3, khv = (id >> 7) & 1, cell = id >> 8;
    const int l = l_lo + cell, t = dg - l;
    const int cur = t & 1, prev = cur ^ 1;
    const size_t row0 = (size_t)(mqv * 64) * HH;
    const __half* a;
    if (khv == 0) {
        if (l == 0) a = g_e + (size_t)t * BB * HH + row0;
        else        a = g_h + ((size_t)cur * LL + (l - 1)) * BB * HH + row0;
    } else {
        a = g_h + ((size_t)prev * LL + l) * BB * HH + row0;
    }
    const __half* w = g_w + ((size_t)l * GG + nb * 64) * KTOT + khv * (NCHL * KC);
    issue_chunk(tb, a + k * KC, w + k * KC, KTOT, tid);
}

// compute one resident chunk into d[4][4]. 8 warps = 4m x 2n, warp tile 16x32.
__device__ __forceinline__ void compute_chunk(float d[4][4], uint32_t tb,
    uint32_t arow128, const uint32_t* brow128, int mask, int a_kb, int b_kb)
{
    #pragma unroll
    for (int s = 0; s < 4; ++s) {
        uint32_t a_[4], w_[2][4];
        const uint32_t akx = (uint32_t)((32 * s + a_kb) ^ mask);
        const uint32_t bkx = (uint32_t)((32 * s + b_kb) ^ mask);
        ldsm4(a_, tb + OFF_A + arow128 + akx);
        #pragma unroll
        for (int nj = 0; nj < 2; ++nj)
            ldsm4(w_[nj], tb + OFF_W + brow128[nj] + bkx);
        #pragma unroll
        for (int nj = 0; nj < 2; ++nj)
            #pragma unroll
            for (int h = 0; h < 2; ++h)
                mma16816(d[nj * 2 + h], a_, &w_[nj][h * 2]);
    }
}

// end-of-task: write partials; if second finisher of the kh-pair, activate inline
__device__ void finish_task(float d[4][4], int id, int dg, int l_lo, int tid,
                            volatile int* done_old_s)
{
    float* mp = g_part + ((size_t)id * NTHR + tid) * 16;
    #pragma unroll
    for (int nf = 0; nf < 4; ++nf)
        *(float4*)(mp + nf * 4) = make_float4(d[nf][0], d[nf][1], d[nf][2], d[nf][3]);
    __threadfence();
    __syncthreads();
    const int nb = id & 31, mqv = (id >> 5) & 3, cell = id >> 8;
    if (tid == 0)
        *done_old_s = (int)atomicAdd(&g_done[dg * 640 + (cell * 4 + mqv) * 32 + nb], 1u);
    __syncthreads();
    if (*done_old_s == 1) {
        const float* pp = g_part + ((size_t)(id ^ 128) * NTHR + tid) * 16;
        float f[4][4];
        #pragma unroll
        for (int nf = 0; nf < 4; ++nf) {
            const float4 p4 = ldcg4(pp + nf * 4);
            f[nf][0] = d[nf][0] + p4.x; f[nf][1] = d[nf][1] + p4.y;
            f[nf][2] = d[nf][2] + p4.z; f[nf][3] = d[nf][3] + p4.w;
        }
        const int l = l_lo + cell;
        const int cur = (dg - l) & 1;
        const int lane = tid & 31, wm = (tid >> 5) & 3, wn = tid >> 7;
        const int trow = wm * 16 + (lane >> 2);
        #pragma unroll
        for (int q = 0; q < 2; ++q) {
            const int cb = wn * 32 + q * 16 + (lane & 3) * 2;
            const int unit = (lane & 3) + 4 * (wn * 2 + q);
            const float b0 = g_bias[l * GG + nb * 64 + cb];
            const float b1 = g_bias[l * GG + nb * 64 + cb + 1];
            const float b2 = g_bias[l * GG + nb * 64 + cb + 8];
            const float b3 = g_bias[l * GG + nb * 64 + cb + 9];
            #pragma unroll
            for (int rr = 0; rr < 2; ++rr) {
                const int row = mqv * 64 + trow + rr * 8;
                const float gi = f[q * 2 + 0][rr * 2 + 0] + b0;
                const float gf = f[q * 2 + 0][rr * 2 + 1] + b1;
                const float gg = f[q * 2 + 1][rr * 2 + 0] + b2;
                const float go = f[q * 2 + 1][rr * 2 + 1] + b3;
                const size_t ci = ((size_t)l * BB + row) * HH + nb * 16 + unit;
                const float cn = sigf(gf) * g_c[ci] + sigf(gi) * tanhft(gg);
                g_c[ci] = cn;
                const float hv = sigf(go) * tanhft(cn);
                g_h[((size_t)cur * LL + l) * BB * HH + (size_t)row * HH + nb * 16 + unit]
                    = __float2half(hv);
            }
        }
    }
    #pragma unroll
    for (int nf = 0; nf < 4; ++nf)
        d[nf][0] = d[nf][1] = d[nf][2] = d[nf][3] = 0.0f;
}

// standalone 4-stage pipelined GEMM (output stage)
__device__ void gemm_mma(float d[4][4], uint32_t sb, int tid, int nch,
    const __half* a0, const __half* w0, int wstride,
    uint32_t arow128, const uint32_t* brow128, int mask, int a_kb, int b_kb)
{
    #pragma unroll
    for (int nf = 0; nf < 4; ++nf)
        #pragma unroll
        for (int r = 0; r < 4; ++r) d[nf][r] = 0.0f;
    #pragma unroll
    for (int p = 0; p < NSTG - 1; ++p)
        if (p < nch)
            issue_chunk(sb + SM_TBASE + p * SM_BUF, a0 + p * KC, w0 + p * KC, wstride, tid);
    #pragma unroll 1
    for (int c = 0; c < nch; ++c) {
        const int rem = nch - 1 - c;
        if (rem >= 2) cp_wait2(); else if (rem == 1) cp_wait1(); else cp_wait0();
        __syncthreads();
        if (c + NSTG - 1 < nch) {
            const int c2 = c + NSTG - 1;
            issue_chunk(sb + SM_TBASE + (c2 & (NSTG - 1)) * SM_BUF,
                        a0 + c2 * KC, w0 + c2 * KC, wstride, tid);
        }
        compute_chunk(d, sb + SM_TBASE + (c & (NSTG - 1)) * SM_BUF,
                      arow128, brow128, mask, a_kb, b_kb);
    }
}

__device__ __forceinline__ void store_gates(float* gs, const float d[4][4], int tid) {
    const int wid = tid >> 5, lane = tid & 31;
    const int wm = wid & 3, wn = wid >> 2;
    const int trow = wm * 16 + (lane >> 2);
    #pragma unroll
    for (int nf = 0; nf < 4; ++nf) {
        const int cc = wn * 32 + nf * 8 + (lane & 3) * 2;
        *(float2*)(gs + trow * GS_STRIDE + cc)       = make_float2(d[nf][0], d[nf][1]);
        *(float2*)(gs + (trow + 8) * GS_STRIDE + cc) = make_float2(d[nf][2], d[nf][3]);
    }
}

// ================= prep kernels =================
// 64-col tile permutation: col c -> gate (c&1)|((c>>3&1)<<1), unit ((c>>1)&3)|((c>>4&3)<<2)
__global__ void prep_w(const float* __restrict__ Wih, const float* __restrict__ Whh) {
    for (int idx = blockIdx.x * blockDim.x + threadIdx.x; idx < LL * GG * KTOT; idx += gridDim.x * blockDim.x) {
        int k = idx & 1023, n = (idx >> 10) & 2047, l = idx >> 21;
        int gate = (n & 1) | (((n >> 3) & 1) << 1);
        int unit = ((n >> 1) & 3) | (((n >> 4) & 3) << 2);
        int src = gate * HH + (n >> 6) * 16 + unit;
        float v = (k < HH) ? Wih[((size_t)l * GG + src) * HH + k]
                           : Whh[((size_t)l * GG + src) * HH + (k - HH)];
        g_w[idx] = __float2half(v);
    }
}
__global__ void prep_b(const float* __restrict__ bih, const float* __restrict__ bhh) {
    for (int idx = blockIdx.x * blockDim.x + threadIdx.x; idx < LL * GG; idx += gridDim.x * blockDim.x) {
        int n = idx & 2047, l = idx >> 11;
        int c = n & 63, tile = n >> 6;
        int gate = (c & 1) | (((c >> 3) & 1) << 1);
        int unit = ((c >> 1) & 3) | (((c >> 4) & 3) << 2);
        int src = gate * HH + tile * 16 + unit;
        g_bias[idx] = bih[l * GG + src] + bhh[l * GG + src];
    }
}
__global__ void prep_wo(const float* __restrict__ Wout) {
    for (size_t idx = blockIdx.x * blockDim.x + threadIdx.x; idx < (size_t)VV * HH; idx += (size_t)gridDim.x * blockDim.x)
        g_wo[idx] = __float2half(Wout[idx]);
}
__global__ void prep_e(const int* __restrict__ x, const float* __restrict__ emb) {
    for (int idx = blockIdx.x * blockDim.x + threadIdx.x; idx < SSTEPS * BB * HH; idx += gridDim.x * blockDim.x) {
        int k = idx & 511, b = (idx >> 9) & 255, t = idx >> 17;
        int tok = x[t * BB + b];   // torch .view(S,B,-1) reinterpretation
        g_e[idx] = __float2half(emb[(size_t)tok * HH + k]);
    }
}

// ================= main persistent kernel =================
__global__ void __launch_bounds__(NTHR, 2)
lstm_mma(const float* __restrict__ h0, const float* __restrict__ c0,
         const float* __restrict__ bout, float* __restrict__ out)
{
    extern __shared__ __align__(1024) char smem[];
    __shared__ int task_q[8];
    __shared__ int done_old_s;
    const uint32_t sb = smem_u32(smem);
    const int tid = threadIdx.x, bid = blockIdx.x;

    const int lane = tid & 31, wid = tid >> 5;
    const int wm = wid & 3, wn = wid >> 2;           // 4m x 2n
    const int mask = (lane & 7) << 4;
    const int a_row = ((lane >> 3) & 1) * 8 + (lane & 7);
    const int a_kb  = ((lane >> 4) & 1) * 16;
    const int b_row = ((lane >> 4) & 1) * 8 + (lane & 7);
    const int b_kb  = ((lane >> 3) & 1) * 16;
    const uint32_t arow128 = (uint32_t)((wm * 16 + a_row) * 128);
    uint32_t brow128[2];
    #pragma unroll
    for (int nj = 0; nj < 2; ++nj)
        brow128[nj] = (uint32_t)((wn * 32 + nj * 16 + b_row) * 128);

    // ---- init: counters, c, h0 ----
    for (int i = bid * NTHR + tid; i < NDIAG; i += NCTA * NTHR) g_tick[i] = 0u;
    for (int i = bid * NTHR + tid; i < NDIAG * 640; i += NCTA * NTHR) g_done[i] = 0u;
    for (int i = bid * NTHR + tid; i < LL * BB * HH; i += NCTA * NTHR) {
        g_c[i] = c0[i];
        g_h[LL * BB * HH + i] = __float2half(h0[i]);
    }
    grid_sync();

    float d[4][4];

    // ======== wavefront over diagonals, work-stealing within each ========
    #pragma unroll 1
    for (int dg = 0; dg < NDIAG; ++dg) {
        const int l_lo = (dg > SSTEPS - 1) ? (dg - (SSTEPS - 1)) : 0;
        const int l_hi = (dg < LL - 1) ? dg : (LL - 1);
        const int ntask = (l_hi - l_lo + 1) << 8;   // ncells * 256

        if (tid == 0) task_q[0] = (int)atomicAdd(&g_tick[dg], 1u);
        __syncthreads();

        int np = 0, cp = 0;
        #pragma unroll
        for (int i = 0; i < NSTG - 1; ++i) {
            const int id0 = task_q[(np >> 3) & 7];
            if (id0 < ntask) {
                issue_task_chunk(sb + SM_TBASE + (np & 3) * SM_BUF, id0, np & 7, dg, l_lo, tid);
                np++;
            }
        }
        #pragma unroll
        for (int nf = 0; nf < 4; ++nf)
            d[nf][0] = d[nf][1] = d[nf][2] = d[nf][3] = 0.0f;

        #pragma unroll 1
        while (true) {
            const int s = cp >> 3;
            const int id = task_q[s & 7];
            if (id >= ntask) break;
            const int infl = np - cp;
            if (infl >= 3) cp_wait2(); else if (infl == 2) cp_wait1(); else cp_wait0();
            __syncthreads();
            if ((cp & 7) == 0 && tid == 0)
                task_q[(s + 1) & 7] = (int)atomicAdd(&g_tick[dg], 1u);
            {
                const int id2 = task_q[(np >> 3) & 7];
                if (id2 < ntask) {
                    issue_task_chunk(sb + SM_TBASE + (np & 3) * SM_BUF, id2, np & 7, dg, l_lo, tid);
                    np++;
                }
            }
            compute_chunk(d, sb + SM_TBASE + (cp & 3) * SM_BUF,
                          arow128, brow128, mask, a_kb, b_kb);
            if ((cp & 7) == 7)
                finish_task(d, id, dg, l_lo, tid, &done_old_s);
            cp++;
        }
        grid_sync();   // diagonal complete: h visible chip-wide
    }

    // ---- output GEMM: logits 256x32000, K=512 -> 4 x 500 = 2000 tiles of 64x64 ----
    float* gs = (float*)(smem + SM_GS);
    const size_t hf = ((size_t)((SSTEPS - 1) & 1) * LL + (LL - 1)) * BB * HH;
    #pragma unroll 1
    for (int tt = bid; tt < 2000; tt += NCTA) {
        const int b0 = (tt / 500) * 64;
        const int v0 = (tt % 500) * 64;
        gemm_mma(d, sb, tid, NCHO,
                 g_h + hf + (size_t)b0 * HH, g_wo + (size_t)v0 * HH, HH,
                 arow128, brow128, mask, a_kb, b_kb);
        store_gates(gs, d, tid);
        __syncthreads();
        {
            const int row = tid >> 2;
            const int c0c = (tid & 3) * 16;
            const float* gr = gs + row * GS_STRIDE + c0c;
            float* op = out + (size_t)(b0 + row) * VV + v0 + c0c;
            #pragma unroll
            for (int c4 = 0; c4 < 4; ++c4) {
                float4 s4;
                s4.x = gr[4*c4+0] + bout[v0 + c0c + 4*c4+0];
                s4.y = gr[4*c4+1] + bout[v0 + c0c + 4*c4+1];
                s4.z = gr[4*c4+2] + bout[v0 + c0c + 4*c4+2];
                s4.w = gr[4*c4+3] + bout[v0 + c0c + 4*c4+3];
                *(float4*)(op + 4*c4) = s4;
            }
        }
        __syncthreads();
    }
}

extern "C" void kernel_launch(void* const* d_in, const int* in_sizes, int n_in,
                              void* d_out, int out_size) {
    (void)in_sizes; (void)n_in; (void)out_size;
    prep_w<<<2048, 256>>>((const float*)d_in[4], (const float*)d_in[5]);
    prep_b<<<40, 256>>>((const float*)d_in[6], (const float*)d_in[7]);
    prep_wo<<<2048, 256>>>((const float*)d_in[8]);
    prep_e<<<2048, 256>>>((const int*)d_in[0], (const float*)d_in[3]);
    cudaFuncSetAttribute(lstm_mma, cudaFuncAttributeMaxDynamicSharedMemorySize, SMEM_TOTAL);
    lstm_mma<<<NCTA, NTHR, SMEM_TOTAL>>>(
        (const float*)d_in[1],   // h0
        (const float*)d_in[2],   // c0
        (const float*)d_in[9],   // b_out
        (float*)d_out);
}